// round 8
// baseline (speedup 1.0000x reference)
#include <cuda_runtime.h>
#include <cuda_bf16.h>
#include <cuda_fp8.h>

// FeaturesLoss: contrastive pairwise loss over N=8192 D=128 fp32 features.
//  pos_term: ANALYTIC per class: sum_c (2 n_c S2_c - 2 ||S1_c||^2).
//  neg_term: hinge fires only if dist_sq < 4; detect via FP8 e4m3 mma.sync Gram
//            (m16n8k32) with conservative slack; flagged pairs recomputed EXACTLY
//            from fp32 X. Persistent CTAs, weighted contiguous chunks, B double-buffer.

#define MARGIN 2.0f
#define EPSV   1e-9f

__device__ double g_pos_sum;
__device__ double g_neg_sum;
__device__ unsigned long long g_num_pos;
__device__ unsigned g_done;
__device__ float g_sq[16384];
__device__ int   g_lab[16384];
__device__ int   g_cnt[64];
__device__ int   g_off[64];
__device__ int   g_list[16384];
__device__ unsigned char g_xb[8192 * 128];   // e4m3

__device__ __forceinline__ unsigned smem_u32(const void* p) {
    unsigned a;
    asm("{ .reg .u64 t; cvta.to.shared.u64 t, %1; cvt.u32.u64 %0, t; }" : "=r"(a) : "l"(p));
    return a;
}
__device__ __forceinline__ void ldsm_x4(unsigned& r0, unsigned& r1, unsigned& r2, unsigned& r3,
                                        unsigned addr) {
    asm volatile("ldmatrix.sync.aligned.m8n8.x4.shared.b16 {%0,%1,%2,%3}, [%4];"
                 : "=r"(r0), "=r"(r1), "=r"(r2), "=r"(r3) : "r"(addr));
}
__device__ __forceinline__ void mma_fp8(float* c, unsigned a0, unsigned a1, unsigned a2,
                                        unsigned a3, unsigned b0, unsigned b1) {
    asm volatile(
        "mma.sync.aligned.m16n8k32.row.col.f32.e4m3.e4m3.f32 "
        "{%0,%1,%2,%3},{%4,%5,%6,%7},{%8,%9},{%0,%1,%2,%3};"
        : "+f"(c[0]), "+f"(c[1]), "+f"(c[2]), "+f"(c[3])
        : "r"(a0), "r"(a1), "r"(a2), "r"(a3), "r"(b0), "r"(b1));
}
#define CP16(dst, src) asm volatile("cp.async.cg.shared.global [%0], [%1], 16;" :: "r"(dst), "l"(src) : "memory")
#define CP_COMMIT()    asm volatile("cp.async.commit_group;" ::: "memory")
#define CP_WAIT0()     asm volatile("cp.async.wait_group 0;" ::: "memory")

// ---------------- prep + hist/lists (one launch) ----------------
__global__ void fl_prep_kernel(const float* __restrict__ X,
                               const int* __restrict__ lab32, int N) {
    if ((int)blockIdx.x == N / 8) {
        __shared__ int cnt[64], soff[64], scur[64];
        __shared__ int hi_nonzero;
        if (threadIdx.x == 0) {
            hi_nonzero = 0; g_pos_sum = 0.0; g_neg_sum = 0.0; g_done = 0;
        }
        if (threadIdx.x < 64) { cnt[threadIdx.x] = 0; scur[threadIdx.x] = 0; }
        __syncthreads();
        int local = 0;
        for (int i = threadIdx.x; i < N / 2; i += blockDim.x)
            if (lab32[2 * i + 1] != 0) local++;
        if (local) atomicAdd(&hi_nonzero, local);
        __syncthreads();
        const bool is_int64 = (hi_nonzero < N / 8);
        for (int i = threadIdx.x; i < N; i += blockDim.x) {
            int l = (is_int64 ? lab32[2 * i] : lab32[i]) & 63;
            g_lab[i] = l;
            atomicAdd(&cnt[l], 1);
        }
        __syncthreads();
        if (threadIdx.x == 0) {
            unsigned long long np = 0;
            int run = 0;
            for (int c = 0; c < 64; c++) {
                np += (unsigned long long)cnt[c] * (unsigned long long)cnt[c];
                soff[c] = run;
                run += cnt[c];
                g_cnt[c] = cnt[c];
            }
            g_num_pos = np;
        }
        __syncthreads();
        if (threadIdx.x < 64) g_off[threadIdx.x] = soff[threadIdx.x];
        for (int i = threadIdx.x; i < N; i += blockDim.x) {
            int l = g_lab[i];
            int p = atomicAdd(&scur[l], 1);
            g_list[soff[l] + p] = i;
        }
        return;
    }
    const int row = blockIdx.x * 8 + (threadIdx.x >> 5);
    const int lane = threadIdx.x & 31;
    float4 v = *(const float4*)&X[(size_t)row * 128 + lane * 4];
    float s = v.x * v.x;
    s = fmaf(v.y, v.y, s);
    s = fmaf(v.z, v.z, s);
    s = fmaf(v.w, v.w, s);
    for (int o = 16; o; o >>= 1) s += __shfl_down_sync(0xffffffffu, s, o);
    if (lane == 0) g_sq[row] = s;
    __nv_fp8x2_storage_t lo = __nv_cvt_float2_to_fp8x2(make_float2(v.x, v.y),
                                                       __NV_SATFINITE, __NV_E4M3);
    __nv_fp8x2_storage_t hi = __nv_cvt_float2_to_fp8x2(make_float2(v.z, v.w),
                                                       __NV_SATFINITE, __NV_E4M3);
    unsigned packed = (unsigned)lo | ((unsigned)hi << 16);
    *(unsigned*)&g_xb[(size_t)row * 128 + lane * 4] = packed;
}

__device__ __forceinline__ int tri_base(int bi, int T) {
    return bi * T - (bi * (bi - 1)) / 2;
}

// ---------------- persistent fp8 mma.sync pairs kernel (D=128, TILE=128) ----------------
#define SROW    144
#define A_OFF   0
#define B0_OFF  (128 * SROW)
#define B1_OFF  (2 * 128 * SROW)
#define MISC    (3 * 128 * SROW)
#define SMEM_DYN (MISC + 256)
#define SLACK_THR 26.0f
#define SLACK_EST 52.0f

__device__ __forceinline__ void load_tile16k(unsigned dstBase, const unsigned char* src, int tid) {
    #pragma unroll
    for (int it = 0; it < 4; it++) {
        int lin = tid + 256 * it;            // 0..1023
        int r = lin >> 3;                    // 0..127
        int cb = (lin & 7) * 16;             // byte offset in row
        CP16(dstBase + r * SROW + cb, (const char*)src + r * 128 + cb);
    }
}
__device__ __forceinline__ void write_min4(int rowBase, float* slot, int tid) {
    if (tid < 128) {
        float v = g_sq[rowBase + tid];
        #pragma unroll
        for (int o = 16; o; o >>= 1) v = fminf(v, __shfl_down_sync(0xffffffffu, v, o));
        if ((tid & 31) == 0) slot[tid >> 5] = v;
    }
}

// Per-class analytic pos sum.
__device__ void class_phase(int c, const float* __restrict__ X, char* sm) {
    int n = g_cnt[c];
    if (n == 0) return;
    int off = g_off[c];
    int tid = threadIdx.x;
    float* scratch = (float*)sm;   // reuse A-tile region before any loads
    if (tid < 128) {
        float s1 = 0.f;
        #pragma unroll 4
        for (int m = 0; m < n; m++)
            s1 += X[(size_t)g_list[off + m] * 128 + tid];
        scratch[tid] = s1 * s1;
    } else {
        float s2 = 0.f;
        for (int m = tid - 128; m < n; m += 128)
            s2 += g_sq[g_list[off + m]];
        for (int o = 16; o; o >>= 1) s2 += __shfl_down_sync(0xffffffffu, s2, o);
        if (((tid - 128) & 31) == 0) scratch[128 + ((tid - 128) >> 5)] = s2;
    }
    __syncthreads();
    if (tid == 0) {
        float s1sq = 0.f;
        for (int d = 0; d < 128; d++) s1sq += scratch[d];
        float S2 = scratch[128] + scratch[129] + scratch[130] + scratch[131];
        double pos_c = 2.0 * (double)n * (double)S2 - 2.0 * (double)s1sq;
        atomicAdd(&g_pos_sum, pos_c);
    }
    __syncthreads();
}

__global__ void __launch_bounds__(256, 2) fl_pairs_mma(int T, int nTiles, int nCTA,
                                                       const float* __restrict__ X,
                                                       float* out, long long N) {
    extern __shared__ char sm[];
    const unsigned sb = smem_u32(sm);
    float* minA = (float*)(sm + MISC);          // [2][4]
    float* minB = (float*)(sm + MISC + 32);     // [2][4]
    float* red  = (float*)(sm + MISC + 64);     // [8]

    const int tid = threadIdx.x;
    const int wid = tid >> 5;
    const int lane = tid & 31;

    for (int cc = blockIdx.x; cc < 64; cc += nCTA)
        class_phase(cc, X, sm);

    // Weighted balanced contiguous chunks: class CTAs (c<64) get W fewer tiles.
    const int c = blockIdx.x;
    const int W = ((nTiles / nCTA) > 2 && nCTA >= 64) ? 2 : 0;
    const int vTotal = nTiles + 64 * W;
    const int vbase = vTotal / nCTA, vrem = vTotal % nCTA;
    const int vstart = c * vbase + min(c, vrem);
    const int vcount = vbase + (c < vrem ? 1 : 0);
    const int start = vstart - W * min(c, 64);
    const int count = vcount - (c < 64 ? W : 0);

    // Warp tiling: 2(M) x 4(N); warp tile 64x32.
    const int Moff = (wid >> 2) * 64;
    const int Noff = (wid & 3) * 32;
    const int arow = (lane & 7) + ((lane >> 3) & 1) * 8;
    const int achk = (lane >> 4) * 16;
    const int brow = (lane & 7) + ((lane >> 4) & 1) * 8;
    const int bchk = ((lane >> 3) & 1) * 16;
    const int grp = lane >> 2, q = lane & 3;

    float ns = 0.f;

    if (count > 0) {
        int bi = 0;
        while (bi < T - 1 && tri_base(bi + 1, T) <= start) bi++;
        int bj = bi + (start - tri_base(bi, T));

        load_tile16k(sb + A_OFF, &g_xb[(size_t)bi * 128 * 128], tid);
        if (bi != bj)
            load_tile16k(sb + B0_OFF, &g_xb[(size_t)bj * 128 * 128], tid);
        CP_COMMIT();
        write_min4(bi * 128, minA, tid);
        write_min4(bj * 128, minB, tid);

        int par = 0;
        for (int s = 0; s < count; s++) {
            const bool diag = (bi == bj);
            const int rowA = bi * 128, rowB = bj * 128;
            int nbj = bj + 1, nbi = bi;
            if (nbj == T) { nbi = bi + 1; nbj = nbi; }
            const bool more = (s + 1 < count);
            const bool aChange = more && (nbi != bi);

            CP_WAIT0();
            __syncthreads();

            // Prefetch next B (only when next tile is off-diagonal; hidden under MMA).
            if (more && !aChange) {
                load_tile16k(sb + (par ? B0_OFF : B1_OFF),
                             &g_xb[(size_t)nbj * 128 * 128], tid);
                CP_COMMIT();
            }
            if (more) write_min4(nbj * 128, minB + (par ^ 1) * 4, tid);

            const unsigned aBase = sb + A_OFF;
            const unsigned bBase = diag ? (sb + A_OFF) : (sb + (par ? B1_OFF : B0_OFF));

            float acc[4][4][4];
            #pragma unroll
            for (int mi = 0; mi < 4; mi++)
                #pragma unroll
                for (int ni = 0; ni < 4; ni++)
                    #pragma unroll
                    for (int v = 0; v < 4; v++) acc[mi][ni][v] = 0.f;

            #pragma unroll
            for (int ks = 0; ks < 4; ks++) {
                const int kbyte = ks * 32;
                unsigned a[4][4];
                #pragma unroll
                for (int mi = 0; mi < 4; mi++) {
                    unsigned ad = aBase + (unsigned)((Moff + mi * 16 + arow) * SROW + kbyte + achk);
                    ldsm_x4(a[mi][0], a[mi][1], a[mi][2], a[mi][3], ad);
                }
                unsigned b[2][4];
                #pragma unroll
                for (int p = 0; p < 2; p++) {
                    unsigned bd = bBase + (unsigned)((Noff + p * 16 + brow) * SROW + kbyte + bchk);
                    ldsm_x4(b[p][0], b[p][1], b[p][2], b[p][3], bd);
                }
                #pragma unroll
                for (int mi = 0; mi < 4; mi++)
                    #pragma unroll
                    for (int ni = 0; ni < 4; ni++)
                        mma_fp8(acc[mi][ni], a[mi][0], a[mi][1], a[mi][2], a[mi][3],
                                b[ni >> 1][(ni & 1) * 2], b[ni >> 1][(ni & 1) * 2 + 1]);
            }

            // A-row change: must wait for all warps' A reads before overwriting.
            if (aChange) {
                __syncthreads();
                load_tile16k(sb + A_OFF, &g_xb[(size_t)nbi * 128 * 128], tid);
                CP_COMMIT();
            }
            if (more) write_min4(nbi * 128, minA + (par ^ 1) * 4, tid);

            // Fast epilogue: hinge possible only if some acc > 0.5*(sqi+sqc)-2-slack.
            float mx = acc[0][0][0];
            #pragma unroll
            for (int mi = 0; mi < 4; mi++)
                #pragma unroll
                for (int ni = 0; ni < 4; ni++)
                    #pragma unroll
                    for (int v = 0; v < 4; v++)
                        mx = fmaxf(mx, acc[mi][ni][v]);
            #pragma unroll
            for (int o = 16; o; o >>= 1)
                mx = fmaxf(mx, __shfl_xor_sync(0xffffffffu, mx, o));
            const float* mA = minA + par * 4;
            const float* mB = minB + par * 4;
            float mnA = fminf(fminf(mA[0], mA[1]), fminf(mA[2], mA[3]));
            float mnB = fminf(fminf(mB[0], mB[1]), fminf(mB[2], mB[3]));
            float thrmin = 0.5f * (mnA + mnB) - 2.0f - SLACK_THR;

            if (mx > thrmin) {
                // Rare path: estimate per element; flagged pairs recomputed exactly.
                #pragma unroll
                for (int mi = 0; mi < 4; mi++) {
                    #pragma unroll
                    for (int ni = 0; ni < 4; ni++) {
                        #pragma unroll
                        for (int rr = 0; rr < 2; rr++) {
                            #pragma unroll
                            for (int cc2 = 0; cc2 < 2; cc2++) {
                                int r = Moff + mi * 16 + grp + rr * 8;
                                int col = Noff + ni * 8 + q * 2 + cc2;
                                float av = acc[mi][ni][rr * 2 + cc2];
                                int ig = rowA + r, jg = rowB + col;
                                float est = g_sq[ig] + g_sq[jg] - 2.f * av;
                                if (est < SLACK_EST) {
                                    if (g_lab[ig] != g_lab[jg] && (!diag || jg > ig)) {
                                        const float* xi = &X[(size_t)ig * 128];
                                        const float* xj = &X[(size_t)jg * 128];
                                        float d = 0.f;
                                        for (int k = 0; k < 128; k++) {
                                            float df = xi[k] - xj[k];
                                            d = fmaf(df, df, d);
                                        }
                                        if (d < 4.f) {
                                            float t = MARGIN - sqrtf(d + EPSV);
                                            if (t > 0.f) ns = fmaf(t, t, ns);
                                        }
                                    }
                                }
                            }
                        }
                    }
                }
            }

            bi = nbi; bj = nbj; par ^= 1;
        }
    }

    // Final reduction + completion.
    for (int o = 16; o; o >>= 1) ns += __shfl_down_sync(0xffffffffu, ns, o);
    if (lane == 0) red[wid] = ns;
    __syncthreads();
    __shared__ unsigned s_last;
    if (tid == 0) {
        float tns = 0.f;
        #pragma unroll
        for (int w = 0; w < 8; w++) tns += red[w];
        if (tns != 0.f) atomicAdd(&g_neg_sum, 2.0 * (double)tns);
        __threadfence();
        s_last = atomicAdd(&g_done, 1u);
    }
    __syncthreads();
    if (tid == 0 && s_last == (unsigned)(nCTA - 1)) {
        double np = (double)g_num_pos;
        double total = (double)N * (double)N;
        double nn = total - np;
        double pt = (np > 0.0) ? 0.5 * g_pos_sum / np : 0.0;
        double nt = (nn > 0.0) ? 0.5 * g_neg_sum / nn : 0.0;
        out[0] = (float)(pt + nt);
        g_done = 0;   // reset for next graph replay
    }
}

// ---------------- fp32 fallback (any D / N) ----------------
__global__ void fl_sq_kernel(const float* __restrict__ X, int N, int D) {
    int row = blockIdx.x;
    float s = 0.f;
    for (int k = threadIdx.x; k < D; k += blockDim.x) {
        float v = X[(size_t)row * D + k];
        s = fmaf(v, v, s);
    }
    for (int o = 16; o; o >>= 1) s += __shfl_down_sync(0xffffffffu, s, o);
    __shared__ float ws[32];
    int lane = threadIdx.x & 31, w = threadIdx.x >> 5;
    if (lane == 0) ws[w] = s;
    __syncthreads();
    if (w == 0) {
        int nw = (blockDim.x + 31) >> 5;
        s = (lane < nw) ? ws[lane] : 0.f;
        for (int o = 16; o; o >>= 1) s += __shfl_down_sync(0xffffffffu, s, o);
        if (lane == 0) g_sq[row] = s;
    }
}

__global__ void fl_hist_kernel(const int* __restrict__ lab32, int N) {
    __shared__ int cnt[64];
    __shared__ int hi_nonzero;
    if (threadIdx.x == 0) { hi_nonzero = 0; g_pos_sum = 0.0; g_neg_sum = 0.0; }
    if (threadIdx.x < 64) cnt[threadIdx.x] = 0;
    __syncthreads();
    int local = 0;
    for (int i = threadIdx.x; i < N / 2; i += blockDim.x)
        if (lab32[2 * i + 1] != 0) local++;
    if (local) atomicAdd(&hi_nonzero, local);
    __syncthreads();
    const bool is_int64 = (hi_nonzero < N / 8);
    for (int i = threadIdx.x; i < N; i += blockDim.x) {
        int l = (is_int64 ? lab32[2 * i] : lab32[i]) & 63;
        g_lab[i] = l;
        atomicAdd(&cnt[l], 1);
    }
    __syncthreads();
    if (threadIdx.x == 0) {
        unsigned long long np = 0;
        for (int c = 0; c < 64; c++)
            np += (unsigned long long)cnt[c] * (unsigned long long)cnt[c];
        g_num_pos = np;
    }
}

__device__ __forceinline__ void tri_decode(int L, int T, int& bi, int& bj) {
    bi = 0;
    while (bi < T - 1 && tri_base(bi + 1, T) <= L) bi++;
    bj = bi + (L - tri_base(bi, T));
}

__global__ __launch_bounds__(256)
void fl_pairs_fp32(const float* __restrict__ X, int N, int D, int T) {
    int bi, bj;
    tri_decode(blockIdx.x, T, bi, bj);
    const int rowA = bi * 64, rowB = bj * 64;
    const bool diag = (bi == bj);
    __shared__ float As[64][65];
    __shared__ float Bs[64][65];
    const int tid = threadIdx.x, tx = tid & 15, ty = tid >> 4;
    float acc[4][4] = {};
    for (int kc = 0; kc < D; kc += 64) {
        __syncthreads();
        #pragma unroll
        for (int i = 0; i < 4; i++) {
            int lin = tid + 256 * i;
            int r = lin >> 4, kq = (lin & 15) << 2;
            if (kc + kq < D) {
                float4 va = *(const float4*)&X[(size_t)(rowA + r) * D + kc + kq];
                As[r][kq] = va.x; As[r][kq + 1] = va.y; As[r][kq + 2] = va.z; As[r][kq + 3] = va.w;
                float4 vb = *(const float4*)&X[(size_t)(rowB + r) * D + kc + kq];
                Bs[r][kq] = vb.x; Bs[r][kq + 1] = vb.y; Bs[r][kq + 2] = vb.z; Bs[r][kq + 3] = vb.w;
            }
        }
        __syncthreads();
        int klim = min(64, D - kc);
        for (int k = 0; k < klim; k++) {
            float a0 = As[ty * 4][k], a1 = As[ty * 4 + 1][k], a2 = As[ty * 4 + 2][k], a3 = As[ty * 4 + 3][k];
            float b0 = Bs[tx * 4][k], b1 = Bs[tx * 4 + 1][k], b2 = Bs[tx * 4 + 2][k], b3 = Bs[tx * 4 + 3][k];
            acc[0][0] = fmaf(a0, b0, acc[0][0]); acc[0][1] = fmaf(a0, b1, acc[0][1]);
            acc[0][2] = fmaf(a0, b2, acc[0][2]); acc[0][3] = fmaf(a0, b3, acc[0][3]);
            acc[1][0] = fmaf(a1, b0, acc[1][0]); acc[1][1] = fmaf(a1, b1, acc[1][1]);
            acc[1][2] = fmaf(a1, b2, acc[1][2]); acc[1][3] = fmaf(a1, b3, acc[1][3]);
            acc[2][0] = fmaf(a2, b0, acc[2][0]); acc[2][1] = fmaf(a2, b1, acc[2][1]);
            acc[2][2] = fmaf(a2, b2, acc[2][2]); acc[2][3] = fmaf(a2, b3, acc[2][3]);
            acc[3][0] = fmaf(a3, b0, acc[3][0]); acc[3][1] = fmaf(a3, b1, acc[3][1]);
            acc[3][2] = fmaf(a3, b2, acc[3][2]); acc[3][3] = fmaf(a3, b3, acc[3][3]);
        }
    }
    const int i0 = rowA + ty * 4, j0 = rowB + tx * 4;
    float sqi[4], sqj[4]; int li[4], lj[4];
    #pragma unroll
    for (int m = 0; m < 4; m++) { sqi[m] = g_sq[i0 + m]; li[m] = g_lab[i0 + m]; }
    #pragma unroll
    for (int n = 0; n < 4; n++) { sqj[n] = g_sq[j0 + n]; lj[n] = g_lab[j0 + n]; }
    float ps = 0.f, nsl = 0.f;
    #pragma unroll
    for (int m = 0; m < 4; m++)
        #pragma unroll
        for (int n = 0; n < 4; n++) {
            if (diag && (j0 + n) <= (i0 + m)) continue;
            float d = fmaxf(sqi[m] + sqj[n] - 2.f * acc[m][n], 0.f);
            if (li[m] == lj[n]) ps += d;
            else { float t = MARGIN - sqrtf(d + EPSV); if (t > 0.f) nsl = fmaf(t, t, nsl); }
        }
    __syncthreads();
    float* red = &As[0][0];
    red[tid] = ps; red[256 + tid] = nsl;
    __syncthreads();
    for (int s = 128; s; s >>= 1) {
        if (tid < s) { red[tid] += red[tid + s]; red[256 + tid] += red[256 + tid + s]; }
        __syncthreads();
    }
    if (tid == 0) {
        atomicAdd(&g_pos_sum, 2.0 * (double)red[0]);
        atomicAdd(&g_neg_sum, 2.0 * (double)red[256]);
    }
}

__global__ void fl_finish_kernel(float* out, long long N) {
    double np = (double)g_num_pos;
    double total = (double)N * (double)N;
    double nn = total - np;
    double pt = (np > 0.0) ? 0.5 * g_pos_sum / np : 0.0;
    double nt = (nn > 0.0) ? 0.5 * g_neg_sum / nn : 0.0;
    out[0] = (float)(pt + nt);
}

extern "C" void kernel_launch(void* const* d_in, const int* in_sizes, int n_in,
                              void* d_out, int out_size) {
    const float* X = (const float*)d_in[0];
    const int* lab32 = (const int*)d_in[1];
    int N = in_sizes[1];
    int D = in_sizes[0] / N;

    if (D == 128 && N % 128 == 0 && (size_t)N * D <= 8192 * 128) {
        fl_prep_kernel<<<N / 8 + 1, 256>>>(X, lab32, N);
        int T = N / 128;
        int nTiles = T * (T + 1) / 2;
        int grid = 296;
        if (grid > nTiles) grid = nTiles;
        cudaFuncSetAttribute(fl_pairs_mma, cudaFuncAttributeMaxDynamicSharedMemorySize, SMEM_DYN);
        fl_pairs_mma<<<grid, 256, SMEM_DYN>>>(T, nTiles, grid, X, (float*)d_out, (long long)N);
    } else {
        fl_sq_kernel<<<N, 128>>>(X, N, D);
        fl_hist_kernel<<<1, 1024>>>(lab32, N);
        int T = (N + 63) / 64;
        int nb = T * (T + 1) / 2;
        fl_pairs_fp32<<<nb, 256>>>(X, N, D, T);
        fl_finish_kernel<<<1, 1>>>((float*)d_out, (long long)N);
    }
}

// round 9
// speedup vs baseline: 1.0318x; 1.0318x over previous
#include <cuda_runtime.h>
#include <cuda_bf16.h>

// FeaturesLoss: contrastive pairwise loss over N=8192 D=128 fp32 features.
//  pos_term: ANALYTIC per class: sum_c (2 n_c S2_c - 2 ||S1_c||^2).
//  neg_term: hinge fires only if dist_sq < 4; detect via bf16 mma.sync Gram tiles
//            vs constant per-CTA threshold (global min of row norms); flagged
//            pairs recomputed EXACTLY from fp32 X.
// Persistent CTAs, weighted contiguous chunks, B double-buffer, low-reg MMA loop.

#define MARGIN 2.0f
#define EPSV   1e-9f
#define SLACK_THR 6.0f
#define SLACK_EST 16.0f

__device__ double g_pos_sum;
__device__ double g_neg_sum;
__device__ unsigned long long g_num_pos;
__device__ unsigned g_done;
__device__ float g_sq[16384];
__device__ int   g_lab[16384];
__device__ int   g_cnt[64];
__device__ int   g_off[64];
__device__ int   g_list[16384];
__device__ __nv_bfloat16 g_xb[8192 * 128];

__device__ __forceinline__ unsigned smem_u32(const void* p) {
    unsigned a;
    asm("{ .reg .u64 t; cvta.to.shared.u64 t, %1; cvt.u32.u64 %0, t; }" : "=r"(a) : "l"(p));
    return a;
}
__device__ __forceinline__ void ldsm_x4(unsigned& r0, unsigned& r1, unsigned& r2, unsigned& r3,
                                        unsigned addr) {
    asm volatile("ldmatrix.sync.aligned.m8n8.x4.shared.b16 {%0,%1,%2,%3}, [%4];"
                 : "=r"(r0), "=r"(r1), "=r"(r2), "=r"(r3) : "r"(addr));
}
__device__ __forceinline__ void mma_bf16(float* c, unsigned a0, unsigned a1, unsigned a2,
                                         unsigned a3, unsigned b0, unsigned b1) {
    asm volatile(
        "mma.sync.aligned.m16n8k16.row.col.f32.bf16.bf16.f32 "
        "{%0,%1,%2,%3},{%4,%5,%6,%7},{%8,%9},{%0,%1,%2,%3};"
        : "+f"(c[0]), "+f"(c[1]), "+f"(c[2]), "+f"(c[3])
        : "r"(a0), "r"(a1), "r"(a2), "r"(a3), "r"(b0), "r"(b1));
}
#define CP16(dst, src) asm volatile("cp.async.cg.shared.global [%0], [%1], 16;" :: "r"(dst), "l"(src) : "memory")
#define CP_COMMIT()    asm volatile("cp.async.commit_group;" ::: "memory")
#define CP_WAIT0()     asm volatile("cp.async.wait_group 0;" ::: "memory")

// ---------------- prep + hist/lists (one launch) ----------------
__global__ void fl_prep_kernel(const float* __restrict__ X,
                               const int* __restrict__ lab32, int N) {
    if ((int)blockIdx.x == N / 8) {
        __shared__ int cnt[64], soff[64], scur[64];
        __shared__ int hi_nonzero;
        if (threadIdx.x == 0) {
            hi_nonzero = 0; g_pos_sum = 0.0; g_neg_sum = 0.0; g_done = 0;
        }
        if (threadIdx.x < 64) { cnt[threadIdx.x] = 0; scur[threadIdx.x] = 0; }
        __syncthreads();
        int local = 0;
        for (int i = threadIdx.x; i < N / 2; i += blockDim.x)
            if (lab32[2 * i + 1] != 0) local++;
        if (local) atomicAdd(&hi_nonzero, local);
        __syncthreads();
        const bool is_int64 = (hi_nonzero < N / 8);
        for (int i = threadIdx.x; i < N; i += blockDim.x) {
            int l = (is_int64 ? lab32[2 * i] : lab32[i]) & 63;
            g_lab[i] = l;
            atomicAdd(&cnt[l], 1);
        }
        __syncthreads();
        if (threadIdx.x == 0) {
            unsigned long long np = 0;
            int run = 0;
            for (int c = 0; c < 64; c++) {
                np += (unsigned long long)cnt[c] * (unsigned long long)cnt[c];
                soff[c] = run;
                run += cnt[c];
                g_cnt[c] = cnt[c];
            }
            g_num_pos = np;
        }
        __syncthreads();
        if (threadIdx.x < 64) g_off[threadIdx.x] = soff[threadIdx.x];
        for (int i = threadIdx.x; i < N; i += blockDim.x) {
            int l = g_lab[i];
            int p = atomicAdd(&scur[l], 1);
            g_list[soff[l] + p] = i;
        }
        return;
    }
    const int row = blockIdx.x * 8 + (threadIdx.x >> 5);
    const int lane = threadIdx.x & 31;
    float4 v = *(const float4*)&X[(size_t)row * 128 + lane * 4];
    float s = v.x * v.x;
    s = fmaf(v.y, v.y, s);
    s = fmaf(v.z, v.z, s);
    s = fmaf(v.w, v.w, s);
    for (int o = 16; o; o >>= 1) s += __shfl_down_sync(0xffffffffu, s, o);
    if (lane == 0) g_sq[row] = s;
    __nv_bfloat162 p0 = __floats2bfloat162_rn(v.x, v.y);
    __nv_bfloat162 p1 = __floats2bfloat162_rn(v.z, v.w);
    uint2 packed;
    packed.x = *(unsigned*)&p0;
    packed.y = *(unsigned*)&p1;
    *(uint2*)&g_xb[(size_t)row * 128 + lane * 4] = packed;
}

__device__ __forceinline__ int tri_base(int bi, int T) {
    return bi * T - (bi * (bi - 1)) / 2;
}

// ---------------- persistent bf16 mma.sync pairs kernel (D=128, TILE=128) ----------------
#define SROW    272
#define A_OFF   0
#define B0_OFF  34816
#define B1_OFF  69632
#define MISC    104448
#define SMEM_DYN (MISC + 640)

__device__ __forceinline__ void load_tile32k(unsigned dstBase, const char* src, int tid) {
    #pragma unroll
    for (int it = 0; it < 8; it++) {
        int lin = tid + 256 * it;            // 0..2047
        int r = lin >> 4;
        int cb = (lin & 15) * 16;
        CP16(dstBase + r * SROW + cb, src + r * 256 + cb);
    }
}

// Per-class analytic pos sum (scratch in MISC region, not the tile buffers).
__device__ void class_phase(int c, const float* __restrict__ X, float* scratch) {
    int n = g_cnt[c];
    if (n == 0) return;
    int off = g_off[c];
    int tid = threadIdx.x;
    if (tid < 128) {
        float s1 = 0.f;
        #pragma unroll 4
        for (int m = 0; m < n; m++)
            s1 += X[(size_t)g_list[off + m] * 128 + tid];
        scratch[tid] = s1 * s1;
    } else {
        float s2 = 0.f;
        for (int m = tid - 128; m < n; m += 128)
            s2 += g_sq[g_list[off + m]];
        for (int o = 16; o; o >>= 1) s2 += __shfl_down_sync(0xffffffffu, s2, o);
        if (((tid - 128) & 31) == 0) scratch[128 + ((tid - 128) >> 5)] = s2;
    }
    __syncthreads();
    if (tid == 0) {
        float s1sq = 0.f;
        for (int d = 0; d < 128; d++) s1sq += scratch[d];
        float S2 = scratch[128] + scratch[129] + scratch[130] + scratch[131];
        double pos_c = 2.0 * (double)n * (double)S2 - 2.0 * (double)s1sq;
        atomicAdd(&g_pos_sum, pos_c);
    }
    __syncthreads();
}

__global__ void __launch_bounds__(256, 2) fl_pairs_mma(int T, int nTiles, int nCTA,
                                                       const float* __restrict__ X,
                                                       float* out, long long N) {
    extern __shared__ char sm[];
    const unsigned sb = smem_u32(sm);
    float* scratch = (float*)(sm + MISC);        // 132 floats (class phase)
    float* red = (float*)(sm + MISC + 544);      // 8 floats

    const int tid = threadIdx.x;
    const int wid = tid >> 5;
    const int lane = tid & 31;

    // Weighted balanced contiguous chunks: class CTAs (c<64) get W fewer tiles.
    const int c = blockIdx.x;
    const int W = ((nTiles / nCTA) > 2 && nCTA >= 64) ? 1 : 0;
    const int vTotal = nTiles + 64 * W;
    const int vbase = vTotal / nCTA, vrem = vTotal % nCTA;
    const int vstart = c * vbase + min(c, vrem);
    const int vcount = vbase + (c < vrem ? 1 : 0);
    const int start = vstart - W * min(c, 64);
    const int count = vcount - (c < 64 ? W : 0);

    // Decode starting tile, issue its loads immediately (fly during class phase).
    int bi = 0, bj = 0;
    if (count > 0) {
        while (bi < T - 1 && tri_base(bi + 1, T) <= start) bi++;
        bj = bi + (start - tri_base(bi, T));
        load_tile32k(sb + A_OFF, (const char*)&g_xb[(size_t)bi * 128 * 128], tid);
        if (bi != bj)
            load_tile32k(sb + B0_OFF, (const char*)&g_xb[(size_t)bj * 128 * 128], tid);
        CP_COMMIT();
    }

    // Per-CTA constant threshold: global min of row norms.
    float gv = 3.4e38f;
    for (int i = tid; i < T * 128; i += 256) gv = fminf(gv, g_sq[i]);
    #pragma unroll
    for (int o = 16; o; o >>= 1) gv = fminf(gv, __shfl_xor_sync(0xffffffffu, gv, o));
    if (lane == 0) red[wid] = gv;
    __syncthreads();
    float gmin = red[0];
    #pragma unroll
    for (int w = 1; w < 8; w++) gmin = fminf(gmin, red[w]);
    const float thrmin = gmin - 2.0f - SLACK_THR;

    for (int cc = blockIdx.x; cc < 64; cc += nCTA)
        class_phase(cc, X, scratch);

    // Warp tiling: 2(M) x 4(N); warp tile 64x32.
    const int Moff = (wid >> 2) * 64;
    const int Noff = (wid & 3) * 32;
    const int arow = (lane & 7) + ((lane >> 3) & 1) * 8;
    const int achk = (lane >> 4) * 16;
    const int brow = (lane & 7) + ((lane >> 4) & 1) * 8;
    const int bchk = ((lane >> 3) & 1) * 16;
    const int grp = lane >> 2, q = lane & 3;

    float ns = 0.f;

    if (count > 0) {
        int par = 0;
        for (int s = 0; s < count; s++) {
            const bool diag = (bi == bj);
            const int rowA = bi * 128, rowB = bj * 128;
            int nbj = bj + 1, nbi = bi;
            if (nbj == T) { nbi = bi + 1; nbj = nbi; }
            const bool more = (s + 1 < count);
            const bool aChange = more && (nbi != bi);

            CP_WAIT0();
            __syncthreads();

            // Prefetch next B (next tile off-diagonal; hidden under this MMA loop).
            if (more && !aChange && nbi != nbj) {
                load_tile32k(sb + (par ? B0_OFF : B1_OFF),
                             (const char*)&g_xb[(size_t)nbj * 128 * 128], tid);
                CP_COMMIT();
            }

            const unsigned aBase = sb + A_OFF;
            const unsigned bBase = diag ? (sb + A_OFF) : (sb + (par ? B1_OFF : B0_OFF));

            float acc[4][4][4];
            #pragma unroll
            for (int mi = 0; mi < 4; mi++)
                #pragma unroll
                for (int ni = 0; ni < 4; ni++)
                    #pragma unroll
                    for (int v = 0; v < 4; v++) acc[mi][ni][v] = 0.f;

            // Low-register MMA loop: B fragments live per-ks, A fragments per-mi.
            #pragma unroll
            for (int ks = 0; ks < 8; ks++) {
                const int kbyte = ks * 32;
                unsigned b[2][4];
                #pragma unroll
                for (int p = 0; p < 2; p++) {
                    unsigned bd = bBase + (unsigned)((Noff + p * 16 + brow) * SROW + kbyte + bchk);
                    ldsm_x4(b[p][0], b[p][1], b[p][2], b[p][3], bd);
                }
                #pragma unroll
                for (int mi = 0; mi < 4; mi++) {
                    unsigned a0, a1, a2, a3;
                    unsigned ad = aBase + (unsigned)((Moff + mi * 16 + arow) * SROW + kbyte + achk);
                    ldsm_x4(a0, a1, a2, a3, ad);
                    #pragma unroll
                    for (int ni = 0; ni < 4; ni++)
                        mma_bf16(acc[mi][ni], a0, a1, a2, a3,
                                 b[ni >> 1][(ni & 1) * 2], b[ni >> 1][(ni & 1) * 2 + 1]);
                }
            }

            // A-row change: wait for all warps' A reads before overwriting.
            if (aChange) {
                __syncthreads();
                load_tile32k(sb + A_OFF, (const char*)&g_xb[(size_t)nbi * 128 * 128], tid);
                CP_COMMIT();
            }

            // Fast epilogue: hinge possible only if some acc exceeds threshold.
            float mx = acc[0][0][0];
            #pragma unroll
            for (int mi = 0; mi < 4; mi++)
                #pragma unroll
                for (int ni = 0; ni < 4; ni++)
                    #pragma unroll
                    for (int v = 0; v < 4; v++)
                        mx = fmaxf(mx, acc[mi][ni][v]);
            #pragma unroll
            for (int o = 16; o; o >>= 1)
                mx = fmaxf(mx, __shfl_xor_sync(0xffffffffu, mx, o));

            if (mx > thrmin) {
                // Rare path: per-element estimate; flagged pairs recomputed exactly.
                #pragma unroll
                for (int mi = 0; mi < 4; mi++) {
                    #pragma unroll
                    for (int ni = 0; ni < 4; ni++) {
                        #pragma unroll
                        for (int rr = 0; rr < 2; rr++) {
                            #pragma unroll
                            for (int cc2 = 0; cc2 < 2; cc2++) {
                                int r = Moff + mi * 16 + grp + rr * 8;
                                int col = Noff + ni * 8 + q * 2 + cc2;
                                float av = acc[mi][ni][rr * 2 + cc2];
                                int ig = rowA + r, jg = rowB + col;
                                float est = g_sq[ig] + g_sq[jg] - 2.f * av;
                                if (est < SLACK_EST) {
                                    if (g_lab[ig] != g_lab[jg] && (!diag || jg > ig)) {
                                        const float* xi = &X[(size_t)ig * 128];
                                        const float* xj = &X[(size_t)jg * 128];
                                        float d = 0.f;
                                        for (int k = 0; k < 128; k++) {
                                            float df = xi[k] - xj[k];
                                            d = fmaf(df, df, d);
                                        }
                                        if (d < 4.f) {
                                            float t = MARGIN - sqrtf(d + EPSV);
                                            if (t > 0.f) ns = fmaf(t, t, ns);
                                        }
                                    }
                                }
                            }
                        }
                    }
                }
            }

            bi = nbi; bj = nbj; par ^= 1;
        }
    }

    // Final reduction + completion.
    for (int o = 16; o; o >>= 1) ns += __shfl_down_sync(0xffffffffu, ns, o);
    __syncthreads();
    if (lane == 0) red[wid] = ns;
    __syncthreads();
    __shared__ unsigned s_last;
    if (tid == 0) {
        float tns = 0.f;
        #pragma unroll
        for (int w = 0; w < 8; w++) tns += red[w];
        if (tns != 0.f) atomicAdd(&g_neg_sum, 2.0 * (double)tns);
        __threadfence();
        s_last = atomicAdd(&g_done, 1u);
    }
    __syncthreads();
    if (tid == 0 && s_last == (unsigned)(nCTA - 1)) {
        double np = (double)g_num_pos;
        double total = (double)N * (double)N;
        double nn = total - np;
        double pt = (np > 0.0) ? 0.5 * g_pos_sum / np : 0.0;
        double nt = (nn > 0.0) ? 0.5 * g_neg_sum / nn : 0.0;
        out[0] = (float)(pt + nt);
        g_done = 0;   // reset for next graph replay
    }
}

// ---------------- fp32 fallback (any D / N) ----------------
__global__ void fl_sq_kernel(const float* __restrict__ X, int N, int D) {
    int row = blockIdx.x;
    float s = 0.f;
    for (int k = threadIdx.x; k < D; k += blockDim.x) {
        float v = X[(size_t)row * D + k];
        s = fmaf(v, v, s);
    }
    for (int o = 16; o; o >>= 1) s += __shfl_down_sync(0xffffffffu, s, o);
    __shared__ float ws[32];
    int lane = threadIdx.x & 31, w = threadIdx.x >> 5;
    if (lane == 0) ws[w] = s;
    __syncthreads();
    if (w == 0) {
        int nw = (blockDim.x + 31) >> 5;
        s = (lane < nw) ? ws[lane] : 0.f;
        for (int o = 16; o; o >>= 1) s += __shfl_down_sync(0xffffffffu, s, o);
        if (lane == 0) g_sq[row] = s;
    }
}

__global__ void fl_hist_kernel(const int* __restrict__ lab32, int N) {
    __shared__ int cnt[64];
    __shared__ int hi_nonzero;
    if (threadIdx.x == 0) { hi_nonzero = 0; g_pos_sum = 0.0; g_neg_sum = 0.0; }
    if (threadIdx.x < 64) cnt[threadIdx.x] = 0;
    __syncthreads();
    int local = 0;
    for (int i = threadIdx.x; i < N / 2; i += blockDim.x)
        if (lab32[2 * i + 1] != 0) local++;
    if (local) atomicAdd(&hi_nonzero, local);
    __syncthreads();
    const bool is_int64 = (hi_nonzero < N / 8);
    for (int i = threadIdx.x; i < N; i += blockDim.x) {
        int l = (is_int64 ? lab32[2 * i] : lab32[i]) & 63;
        g_lab[i] = l;
        atomicAdd(&cnt[l], 1);
    }
    __syncthreads();
    if (threadIdx.x == 0) {
        unsigned long long np = 0;
        for (int c = 0; c < 64; c++)
            np += (unsigned long long)cnt[c] * (unsigned long long)cnt[c];
        g_num_pos = np;
    }
}

__device__ __forceinline__ void tri_decode(int L, int T, int& bi, int& bj) {
    bi = 0;
    while (bi < T - 1 && tri_base(bi + 1, T) <= L) bi++;
    bj = bi + (L - tri_base(bi, T));
}

__global__ __launch_bounds__(256)
void fl_pairs_fp32(const float* __restrict__ X, int N, int D, int T) {
    int bi, bj;
    tri_decode(blockIdx.x, T, bi, bj);
    const int rowA = bi * 64, rowB = bj * 64;
    const bool diag = (bi == bj);
    __shared__ float As[64][65];
    __shared__ float Bs[64][65];
    const int tid = threadIdx.x, tx = tid & 15, ty = tid >> 4;
    float acc[4][4] = {};
    for (int kc = 0; kc < D; kc += 64) {
        __syncthreads();
        #pragma unroll
        for (int i = 0; i < 4; i++) {
            int lin = tid + 256 * i;
            int r = lin >> 4, kq = (lin & 15) << 2;
            if (kc + kq < D) {
                float4 va = *(const float4*)&X[(size_t)(rowA + r) * D + kc + kq];
                As[r][kq] = va.x; As[r][kq + 1] = va.y; As[r][kq + 2] = va.z; As[r][kq + 3] = va.w;
                float4 vb = *(const float4*)&X[(size_t)(rowB + r) * D + kc + kq];
                Bs[r][kq] = vb.x; Bs[r][kq + 1] = vb.y; Bs[r][kq + 2] = vb.z; Bs[r][kq + 3] = vb.w;
            }
        }
        __syncthreads();
        int klim = min(64, D - kc);
        for (int k = 0; k < klim; k++) {
            float a0 = As[ty * 4][k], a1 = As[ty * 4 + 1][k], a2 = As[ty * 4 + 2][k], a3 = As[ty * 4 + 3][k];
            float b0 = Bs[tx * 4][k], b1 = Bs[tx * 4 + 1][k], b2 = Bs[tx * 4 + 2][k], b3 = Bs[tx * 4 + 3][k];
            acc[0][0] = fmaf(a0, b0, acc[0][0]); acc[0][1] = fmaf(a0, b1, acc[0][1]);
            acc[0][2] = fmaf(a0, b2, acc[0][2]); acc[0][3] = fmaf(a0, b3, acc[0][3]);
            acc[1][0] = fmaf(a1, b0, acc[1][0]); acc[1][1] = fmaf(a1, b1, acc[1][1]);
            acc[1][2] = fmaf(a1, b2, acc[1][2]); acc[1][3] = fmaf(a1, b3, acc[1][3]);
            acc[2][0] = fmaf(a2, b0, acc[2][0]); acc[2][1] = fmaf(a2, b1, acc[2][1]);
            acc[2][2] = fmaf(a2, b2, acc[2][2]); acc[2][3] = fmaf(a2, b3, acc[2][3]);
            acc[3][0] = fmaf(a3, b0, acc[3][0]); acc[3][1] = fmaf(a3, b1, acc[3][1]);
            acc[3][2] = fmaf(a3, b2, acc[3][2]); acc[3][3] = fmaf(a3, b3, acc[3][3]);
        }
    }
    const int i0 = rowA + ty * 4, j0 = rowB + tx * 4;
    float sqi[4], sqj[4]; int li[4], lj[4];
    #pragma unroll
    for (int m = 0; m < 4; m++) { sqi[m] = g_sq[i0 + m]; li[m] = g_lab[i0 + m]; }
    #pragma unroll
    for (int n = 0; n < 4; n++) { sqj[n] = g_sq[j0 + n]; lj[n] = g_lab[j0 + n]; }
    float ps = 0.f, nsl = 0.f;
    #pragma unroll
    for (int m = 0; m < 4; m++)
        #pragma unroll
        for (int n = 0; n < 4; n++) {
            if (diag && (j0 + n) <= (i0 + m)) continue;
            float d = fmaxf(sqi[m] + sqj[n] - 2.f * acc[m][n], 0.f);
            if (li[m] == lj[n]) ps += d;
            else { float t = MARGIN - sqrtf(d + EPSV); if (t > 0.f) nsl = fmaf(t, t, nsl); }
        }
    __syncthreads();
    float* red = &As[0][0];
    red[tid] = ps; red[256 + tid] = nsl;
    __syncthreads();
    for (int s = 128; s; s >>= 1) {
        if (tid < s) { red[tid] += red[tid + s]; red[256 + tid] += red[256 + tid + s]; }
        __syncthreads();
    }
    if (tid == 0) {
        atomicAdd(&g_pos_sum, 2.0 * (double)red[0]);
        atomicAdd(&g_neg_sum, 2.0 * (double)red[256]);
    }
}

__global__ void fl_finish_kernel(float* out, long long N) {
    double np = (double)g_num_pos;
    double total = (double)N * (double)N;
    double nn = total - np;
    double pt = (np > 0.0) ? 0.5 * g_pos_sum / np : 0.0;
    double nt = (nn > 0.0) ? 0.5 * g_neg_sum / nn : 0.0;
    out[0] = (float)(pt + nt);
}

extern "C" void kernel_launch(void* const* d_in, const int* in_sizes, int n_in,
                              void* d_out, int out_size) {
    const float* X = (const float*)d_in[0];
    const int* lab32 = (const int*)d_in[1];
    int N = in_sizes[1];
    int D = in_sizes[0] / N;

    if (D == 128 && N % 128 == 0 && (size_t)N * D <= 8192 * 128) {
        fl_prep_kernel<<<N / 8 + 1, 256>>>(X, lab32, N);
        int T = N / 128;
        int nTiles = T * (T + 1) / 2;
        int grid = 296;
        if (grid > nTiles) grid = nTiles;
        cudaFuncSetAttribute(fl_pairs_mma, cudaFuncAttributeMaxDynamicSharedMemorySize, SMEM_DYN);
        fl_pairs_mma<<<grid, 256, SMEM_DYN>>>(T, nTiles, grid, X, (float*)d_out, (long long)N);
    } else {
        fl_sq_kernel<<<N, 128>>>(X, N, D);
        fl_hist_kernel<<<1, 1024>>>(lab32, N);
        int T = (N + 63) / 64;
        int nb = T * (T + 1) / 2;
        fl_pairs_fp32<<<nb, 256>>>(X, N, D, T);
        fl_finish_kernel<<<1, 1>>>((float*)d_out, (long long)N);
    }
}

// round 10
// speedup vs baseline: 1.0603x; 1.0277x over previous
#include <cuda_runtime.h>
#include <cuda_bf16.h>

// FeaturesLoss: contrastive pairwise loss over N=8192 D=128 fp32 features.
//  pos_term: ANALYTIC per class: sum_c (2 n_c S2_c - 2 ||S1_c||^2).
//  neg_term: hinge fires only if dist_sq < 4; detect via bf16 mma.sync Gram tiles
//            vs constant threshold (global min row norm, computed in prep);
//            flagged pairs recomputed EXACTLY from fp32 X.
// Persistent CTAs, 128x64 tiles (3 CTAs/SM = 24 warps), B double-buffer,
// diagonal tiles alias B onto the A tile.

#define MARGIN 2.0f
#define EPSV   1e-9f
#define SLACK_THR 6.0f
#define SLACK_EST 16.0f

__device__ double g_pos_sum;
__device__ double g_neg_sum;
__device__ unsigned long long g_num_pos;
__device__ unsigned g_done;
__device__ int g_thr_bits = 0x7f7fffff;
__device__ float g_sq[16384];
__device__ int   g_lab[16384];
__device__ int   g_cnt[64];
__device__ int   g_off[64];
__device__ int   g_list[16384];
__device__ __nv_bfloat16 g_xb[8192 * 128];

__device__ __forceinline__ unsigned smem_u32(const void* p) {
    unsigned a;
    asm("{ .reg .u64 t; cvta.to.shared.u64 t, %1; cvt.u32.u64 %0, t; }" : "=r"(a) : "l"(p));
    return a;
}
__device__ __forceinline__ void ldsm_x4(unsigned& r0, unsigned& r1, unsigned& r2, unsigned& r3,
                                        unsigned addr) {
    asm volatile("ldmatrix.sync.aligned.m8n8.x4.shared.b16 {%0,%1,%2,%3}, [%4];"
                 : "=r"(r0), "=r"(r1), "=r"(r2), "=r"(r3) : "r"(addr));
}
__device__ __forceinline__ void mma_bf16(float* c, unsigned a0, unsigned a1, unsigned a2,
                                         unsigned a3, unsigned b0, unsigned b1) {
    asm volatile(
        "mma.sync.aligned.m16n8k16.row.col.f32.bf16.bf16.f32 "
        "{%0,%1,%2,%3},{%4,%5,%6,%7},{%8,%9},{%0,%1,%2,%3};"
        : "+f"(c[0]), "+f"(c[1]), "+f"(c[2]), "+f"(c[3])
        : "r"(a0), "r"(a1), "r"(a2), "r"(a3), "r"(b0), "r"(b1));
}
#define CP16(dst, src) asm volatile("cp.async.cg.shared.global [%0], [%1], 16;" :: "r"(dst), "l"(src) : "memory")
#define CP_COMMIT()    asm volatile("cp.async.commit_group;" ::: "memory")
#define CP_WAIT0()     asm volatile("cp.async.wait_group 0;" ::: "memory")

// ---------------- prep + hist/lists (one launch) ----------------
__global__ void fl_prep_kernel(const float* __restrict__ X,
                               const int* __restrict__ lab32, int N) {
    if ((int)blockIdx.x == N / 8) {
        __shared__ int cnt[64], soff[64], scur[64];
        __shared__ int hi_nonzero;
        if (threadIdx.x == 0) {
            hi_nonzero = 0; g_pos_sum = 0.0; g_neg_sum = 0.0; g_done = 0;
        }
        if (threadIdx.x < 64) { cnt[threadIdx.x] = 0; scur[threadIdx.x] = 0; }
        __syncthreads();
        int local = 0;
        for (int i = threadIdx.x; i < N / 2; i += blockDim.x)
            if (lab32[2 * i + 1] != 0) local++;
        if (local) atomicAdd(&hi_nonzero, local);
        __syncthreads();
        const bool is_int64 = (hi_nonzero < N / 8);
        for (int i = threadIdx.x; i < N; i += blockDim.x) {
            int l = (is_int64 ? lab32[2 * i] : lab32[i]) & 63;
            g_lab[i] = l;
            atomicAdd(&cnt[l], 1);
        }
        __syncthreads();
        if (threadIdx.x == 0) {
            unsigned long long np = 0;
            int run = 0;
            for (int c = 0; c < 64; c++) {
                np += (unsigned long long)cnt[c] * (unsigned long long)cnt[c];
                soff[c] = run;
                run += cnt[c];
                g_cnt[c] = cnt[c];
            }
            g_num_pos = np;
        }
        __syncthreads();
        if (threadIdx.x < 64) g_off[threadIdx.x] = soff[threadIdx.x];
        for (int i = threadIdx.x; i < N; i += blockDim.x) {
            int l = g_lab[i];
            int p = atomicAdd(&scur[l], 1);
            g_list[soff[l] + p] = i;
        }
        return;
    }
    __shared__ float wmin[8];
    const int w = threadIdx.x >> 5;
    const int row = blockIdx.x * 8 + w;
    const int lane = threadIdx.x & 31;
    float4 v = *(const float4*)&X[(size_t)row * 128 + lane * 4];
    float s = v.x * v.x;
    s = fmaf(v.y, v.y, s);
    s = fmaf(v.z, v.z, s);
    s = fmaf(v.w, v.w, s);
    for (int o = 16; o; o >>= 1) s += __shfl_down_sync(0xffffffffu, s, o);
    if (lane == 0) { g_sq[row] = s; wmin[w] = s; }
    __nv_bfloat162 p0 = __floats2bfloat162_rn(v.x, v.y);
    __nv_bfloat162 p1 = __floats2bfloat162_rn(v.z, v.w);
    uint2 packed;
    packed.x = *(unsigned*)&p0;
    packed.y = *(unsigned*)&p1;
    *(uint2*)&g_xb[(size_t)row * 128 + lane * 4] = packed;
    __syncthreads();
    if (threadIdx.x == 0) {
        float m = wmin[0];
        #pragma unroll
        for (int i = 1; i < 8; i++) m = fminf(m, wmin[i]);
        atomicMin(&g_thr_bits, __float_as_int(m));
    }
}

// tiles: 128-row x 64-col over the upper triangle. Row r (0..TR-1) owns col
// tiles c in [2r, TC); base(r) = TC*r - r*(r-1).
__device__ __forceinline__ int tri_base2(int r, int TC) {
    return TC * r - r * (r - 1);
}

// ---------------- persistent bf16 mma.sync pairs kernel (D=128) ----------------
#define SROW    272
#define A_OFF   0
#define B0_OFF  34816
#define B1_OFF  52224
#define MISC    69632
#define SMEM_DYN (MISC + 640)

__device__ __forceinline__ void load_tileA(unsigned dstBase, const char* src, int tid) {
    #pragma unroll
    for (int it = 0; it < 8; it++) {
        int lin = tid + 256 * it;            // 0..2047
        int r = lin >> 4;
        int cb = (lin & 15) * 16;
        CP16(dstBase + r * SROW + cb, src + r * 256 + cb);
    }
}
__device__ __forceinline__ void load_tileB(unsigned dstBase, const char* src, int tid) {
    #pragma unroll
    for (int it = 0; it < 4; it++) {
        int lin = tid + 256 * it;            // 0..1023
        int r = lin >> 4;                    // 0..63
        int cb = (lin & 15) * 16;
        CP16(dstBase + r * SROW + cb, src + r * 256 + cb);
    }
}

// Per-class analytic pos sum.
__device__ void class_phase(int c, const float* __restrict__ X, float* scratch) {
    int n = g_cnt[c];
    if (n == 0) return;
    int off = g_off[c];
    int tid = threadIdx.x;
    if (tid < 128) {
        float s1 = 0.f;
        #pragma unroll 4
        for (int m = 0; m < n; m++)
            s1 += X[(size_t)g_list[off + m] * 128 + tid];
        scratch[tid] = s1 * s1;
    } else {
        float s2 = 0.f;
        for (int m = tid - 128; m < n; m += 128)
            s2 += g_sq[g_list[off + m]];
        for (int o = 16; o; o >>= 1) s2 += __shfl_down_sync(0xffffffffu, s2, o);
        if (((tid - 128) & 31) == 0) scratch[128 + ((tid - 128) >> 5)] = s2;
    }
    __syncthreads();
    if (tid == 0) {
        float s1sq = 0.f;
        for (int d = 0; d < 128; d++) s1sq += scratch[d];
        float S2 = scratch[128] + scratch[129] + scratch[130] + scratch[131];
        double pos_c = 2.0 * (double)n * (double)S2 - 2.0 * (double)s1sq;
        atomicAdd(&g_pos_sum, pos_c);
    }
    __syncthreads();
}

__global__ void __launch_bounds__(256, 3) fl_pairs_mma(int TR, int TC, int nTiles, int nCTA,
                                                       const float* __restrict__ X,
                                                       float* out, long long N) {
    extern __shared__ char sm[];
    const unsigned sb = smem_u32(sm);
    float* scratch = (float*)(sm + MISC);        // 132 floats (class phase)
    float* red = (float*)(sm + MISC + 544);      // 8 floats

    const int tid = threadIdx.x;
    const int wid = tid >> 5;
    const int lane = tid & 31;

    // Weighted contiguous chunks: class CTAs (cta<64) get 1 fewer tile.
    const int cta = blockIdx.x;
    const int W = ((nTiles / nCTA) > 2 && nCTA >= 64) ? 1 : 0;
    const int vTotal = nTiles + 64 * W;
    const int vbase = vTotal / nCTA, vrem = vTotal % nCTA;
    const int vstart = cta * vbase + min(cta, vrem);
    const int vcount = vbase + (cta < vrem ? 1 : 0);
    const int start = vstart - W * min(cta, 64);
    const int count = vcount - (cta < 64 ? W : 0);

    // Decode starting tile; issue its loads before the class phase.
    int r = 0, c = 0;
    if (count > 0) {
        while (r < TR - 1 && tri_base2(r + 1, TC) <= start) r++;
        c = 2 * r + (start - tri_base2(r, TC));
        load_tileA(sb + A_OFF, (const char*)&g_xb[(size_t)r * 128 * 128], tid);
        if ((c >> 1) != r)
            load_tileB(sb + B0_OFF, (const char*)&g_xb[(size_t)c * 64 * 128], tid);
        CP_COMMIT();
    }

    const float gmin = __int_as_float(g_thr_bits);
    const float thrmin = gmin - 2.0f - SLACK_THR;

    for (int cc = blockIdx.x; cc < 64; cc += nCTA)
        class_phase(cc, X, scratch);

    // Warp tiling: 4(M) x 2(N) warps; warp tile 32x32.
    const int Moff = (wid >> 1) * 32;
    const int Noff = (wid & 1) * 32;
    const int arow = (lane & 7) + ((lane >> 3) & 1) * 8;
    const int achk = (lane >> 4) * 16;
    const int brow = (lane & 7) + ((lane >> 4) & 1) * 8;
    const int bchk = ((lane >> 3) & 1) * 16;
    const int grp = lane >> 2, q = lane & 3;

    float ns = 0.f;

    if (count > 0) {
        for (int s = 0; s < count; s++) {
            const bool diag = ((c >> 1) == r);
            const int rowA = r * 128, colB = c * 64;
            int nc = c + 1, nr = r;
            if (nc == TC) { nr = r + 1; nc = 2 * nr; }
            const bool more = (s + 1 < count);
            const bool aChange = more && (nr != r);
            const bool nextDiag = ((nc >> 1) == nr);

            CP_WAIT0();
            __syncthreads();

            // Prefetch next B (next tile non-diag, same row; hidden under MMA).
            if (more && !nextDiag) {
                load_tileB(sb + (((s + 1) & 1) ? B1_OFF : B0_OFF),
                           (const char*)&g_xb[(size_t)nc * 64 * 128], tid);
                CP_COMMIT();
            }

            const unsigned aBase = sb + A_OFF;
            const unsigned bBase = diag ? (aBase + (unsigned)((c - 2 * r) * 64 * SROW))
                                        : (sb + (((s & 1)) ? B1_OFF : B0_OFF));

            float acc[2][4][4];
            #pragma unroll
            for (int mi = 0; mi < 2; mi++)
                #pragma unroll
                for (int ni = 0; ni < 4; ni++)
                    #pragma unroll
                    for (int v = 0; v < 4; v++) acc[mi][ni][v] = 0.f;

            #pragma unroll
            for (int ks = 0; ks < 8; ks++) {
                const int kbyte = ks * 32;
                unsigned b[2][4];
                #pragma unroll
                for (int p = 0; p < 2; p++) {
                    unsigned bd = bBase + (unsigned)((Noff + p * 16 + brow) * SROW + kbyte + bchk);
                    ldsm_x4(b[p][0], b[p][1], b[p][2], b[p][3], bd);
                }
                #pragma unroll
                for (int mi = 0; mi < 2; mi++) {
                    unsigned a0, a1, a2, a3;
                    unsigned ad = aBase + (unsigned)((Moff + mi * 16 + arow) * SROW + kbyte + achk);
                    ldsm_x4(a0, a1, a2, a3, ad);
                    #pragma unroll
                    for (int ni = 0; ni < 4; ni++)
                        mma_bf16(acc[mi][ni], a0, a1, a2, a3,
                                 b[ni >> 1][(ni & 1) * 2], b[ni >> 1][(ni & 1) * 2 + 1]);
                }
            }

            // A-row change: wait for all warps' A reads before overwriting.
            if (aChange) {
                __syncthreads();
                load_tileA(sb + A_OFF, (const char*)&g_xb[(size_t)nr * 128 * 128], tid);
                CP_COMMIT();
            }

            // Fast epilogue: hinge possible only if some acc exceeds threshold.
            float mx = acc[0][0][0];
            #pragma unroll
            for (int mi = 0; mi < 2; mi++)
                #pragma unroll
                for (int ni = 0; ni < 4; ni++)
                    #pragma unroll
                    for (int v = 0; v < 4; v++)
                        mx = fmaxf(mx, acc[mi][ni][v]);
            #pragma unroll
            for (int o = 16; o; o >>= 1)
                mx = fmaxf(mx, __shfl_xor_sync(0xffffffffu, mx, o));

            if (mx > thrmin) {
                // Rare path: per-element estimate; flagged pairs recomputed exactly.
                #pragma unroll
                for (int mi = 0; mi < 2; mi++) {
                    #pragma unroll
                    for (int ni = 0; ni < 4; ni++) {
                        #pragma unroll
                        for (int rr = 0; rr < 2; rr++) {
                            #pragma unroll
                            for (int cc2 = 0; cc2 < 2; cc2++) {
                                int rl = Moff + mi * 16 + grp + rr * 8;
                                int cl = Noff + ni * 8 + q * 2 + cc2;
                                float av = acc[mi][ni][rr * 2 + cc2];
                                int ig = rowA + rl, jg = colB + cl;
                                float est = g_sq[ig] + g_sq[jg] - 2.f * av;
                                if (est < SLACK_EST) {
                                    if (g_lab[ig] != g_lab[jg] && (!diag || jg > ig)) {
                                        const float* xi = &X[(size_t)ig * 128];
                                        const float* xj = &X[(size_t)jg * 128];
                                        float d = 0.f;
                                        for (int k = 0; k < 128; k++) {
                                            float df = xi[k] - xj[k];
                                            d = fmaf(df, df, d);
                                        }
                                        if (d < 4.f) {
                                            float t = MARGIN - sqrtf(d + EPSV);
                                            if (t > 0.f) ns = fmaf(t, t, ns);
                                        }
                                    }
                                }
                            }
                        }
                    }
                }
            }

            r = nr; c = nc;
        }
    }

    // Final reduction + completion.
    for (int o = 16; o; o >>= 1) ns += __shfl_down_sync(0xffffffffu, ns, o);
    __syncthreads();
    if (lane == 0) red[wid] = ns;
    __syncthreads();
    __shared__ unsigned s_last;
    if (tid == 0) {
        float tns = 0.f;
        #pragma unroll
        for (int w = 0; w < 8; w++) tns += red[w];
        if (tns != 0.f) atomicAdd(&g_neg_sum, 2.0 * (double)tns);
        __threadfence();
        s_last = atomicAdd(&g_done, 1u);
    }
    __syncthreads();
    if (tid == 0 && s_last == (unsigned)(nCTA - 1)) {
        double np = (double)g_num_pos;
        double total = (double)N * (double)N;
        double nn = total - np;
        double pt = (np > 0.0) ? 0.5 * g_pos_sum / np : 0.0;
        double nt = (nn > 0.0) ? 0.5 * g_neg_sum / nn : 0.0;
        out[0] = (float)(pt + nt);
        g_done = 0;                 // reset for next graph replay
        g_thr_bits = 0x7f7fffff;    // reset threshold accumulator
    }
}

// ---------------- fp32 fallback (any D / N) ----------------
__global__ void fl_sq_kernel(const float* __restrict__ X, int N, int D) {
    int row = blockIdx.x;
    float s = 0.f;
    for (int k = threadIdx.x; k < D; k += blockDim.x) {
        float v = X[(size_t)row * D + k];
        s = fmaf(v, v, s);
    }
    for (int o = 16; o; o >>= 1) s += __shfl_down_sync(0xffffffffu, s, o);
    __shared__ float ws[32];
    int lane = threadIdx.x & 31, w = threadIdx.x >> 5;
    if (lane == 0) ws[w] = s;
    __syncthreads();
    if (w == 0) {
        int nw = (blockDim.x + 31) >> 5;
        s = (lane < nw) ? ws[lane] : 0.f;
        for (int o = 16; o; o >>= 1) s += __shfl_down_sync(0xffffffffu, s, o);
        if (lane == 0) g_sq[row] = s;
    }
}

__global__ void fl_hist_kernel(const int* __restrict__ lab32, int N) {
    __shared__ int cnt[64];
    __shared__ int hi_nonzero;
    if (threadIdx.x == 0) { hi_nonzero = 0; g_pos_sum = 0.0; g_neg_sum = 0.0; }
    if (threadIdx.x < 64) cnt[threadIdx.x] = 0;
    __syncthreads();
    int local = 0;
    for (int i = threadIdx.x; i < N / 2; i += blockDim.x)
        if (lab32[2 * i + 1] != 0) local++;
    if (local) atomicAdd(&hi_nonzero, local);
    __syncthreads();
    const bool is_int64 = (hi_nonzero < N / 8);
    for (int i = threadIdx.x; i < N; i += blockDim.x) {
        int l = (is_int64 ? lab32[2 * i] : lab32[i]) & 63;
        g_lab[i] = l;
        atomicAdd(&cnt[l], 1);
    }
    __syncthreads();
    if (threadIdx.x == 0) {
        unsigned long long np = 0;
        for (int c = 0; c < 64; c++)
            np += (unsigned long long)cnt[c] * (unsigned long long)cnt[c];
        g_num_pos = np;
    }
}

__device__ __forceinline__ int tri_base(int bi, int T) {
    return bi * T - (bi * (bi - 1)) / 2;
}
__device__ __forceinline__ void tri_decode(int L, int T, int& bi, int& bj) {
    bi = 0;
    while (bi < T - 1 && tri_base(bi + 1, T) <= L) bi++;
    bj = bi + (L - tri_base(bi, T));
}

__global__ __launch_bounds__(256)
void fl_pairs_fp32(const float* __restrict__ X, int N, int D, int T) {
    int bi, bj;
    tri_decode(blockIdx.x, T, bi, bj);
    const int rowA = bi * 64, rowB = bj * 64;
    const bool diag = (bi == bj);
    __shared__ float As[64][65];
    __shared__ float Bs[64][65];
    const int tid = threadIdx.x, tx = tid & 15, ty = tid >> 4;
    float acc[4][4] = {};
    for (int kc = 0; kc < D; kc += 64) {
        __syncthreads();
        #pragma unroll
        for (int i = 0; i < 4; i++) {
            int lin = tid + 256 * i;
            int r = lin >> 4, kq = (lin & 15) << 2;
            if (kc + kq < D) {
                float4 va = *(const float4*)&X[(size_t)(rowA + r) * D + kc + kq];
                As[r][kq] = va.x; As[r][kq + 1] = va.y; As[r][kq + 2] = va.z; As[r][kq + 3] = va.w;
                float4 vb = *(const float4*)&X[(size_t)(rowB + r) * D + kc + kq];
                Bs[r][kq] = vb.x; Bs[r][kq + 1] = vb.y; Bs[r][kq + 2] = vb.z; Bs[r][kq + 3] = vb.w;
            }
        }
        __syncthreads();
        int klim = min(64, D - kc);
        for (int k = 0; k < klim; k++) {
            float a0 = As[ty * 4][k], a1 = As[ty * 4 + 1][k], a2 = As[ty * 4 + 2][k], a3 = As[ty * 4 + 3][k];
            float b0 = Bs[tx * 4][k], b1 = Bs[tx * 4 + 1][k], b2 = Bs[tx * 4 + 2][k], b3 = Bs[tx * 4 + 3][k];
            acc[0][0] = fmaf(a0, b0, acc[0][0]); acc[0][1] = fmaf(a0, b1, acc[0][1]);
            acc[0][2] = fmaf(a0, b2, acc[0][2]); acc[0][3] = fmaf(a0, b3, acc[0][3]);
            acc[1][0] = fmaf(a1, b0, acc[1][0]); acc[1][1] = fmaf(a1, b1, acc[1][1]);
            acc[1][2] = fmaf(a1, b2, acc[1][2]); acc[1][3] = fmaf(a1, b3, acc[1][3]);
            acc[2][0] = fmaf(a2, b0, acc[2][0]); acc[2][1] = fmaf(a2, b1, acc[2][1]);
            acc[2][2] = fmaf(a2, b2, acc[2][2]); acc[2][3] = fmaf(a2, b3, acc[2][3]);
            acc[3][0] = fmaf(a3, b0, acc[3][0]); acc[3][1] = fmaf(a3, b1, acc[3][1]);
            acc[3][2] = fmaf(a3, b2, acc[3][2]); acc[3][3] = fmaf(a3, b3, acc[3][3]);
        }
    }
    const int i0 = rowA + ty * 4, j0 = rowB + tx * 4;
    float sqi[4], sqj[4]; int li[4], lj[4];
    #pragma unroll
    for (int m = 0; m < 4; m++) { sqi[m] = g_sq[i0 + m]; li[m] = g_lab[i0 + m]; }
    #pragma unroll
    for (int n = 0; n < 4; n++) { sqj[n] = g_sq[j0 + n]; lj[n] = g_lab[j0 + n]; }
    float ps = 0.f, nsl = 0.f;
    #pragma unroll
    for (int m = 0; m < 4; m++)
        #pragma unroll
        for (int n = 0; n < 4; n++) {
            if (diag && (j0 + n) <= (i0 + m)) continue;
            float d = fmaxf(sqi[m] + sqj[n] - 2.f * acc[m][n], 0.f);
            if (li[m] == lj[n]) ps += d;
            else { float t = MARGIN - sqrtf(d + EPSV); if (t > 0.f) nsl = fmaf(t, t, nsl); }
        }
    __syncthreads();
    float* red = &As[0][0];
    red[tid] = ps; red[256 + tid] = nsl;
    __syncthreads();
    for (int s = 128; s; s >>= 1) {
        if (tid < s) { red[tid] += red[tid + s]; red[256 + tid] += red[256 + tid + s]; }
        __syncthreads();
    }
    if (tid == 0) {
        atomicAdd(&g_pos_sum, 2.0 * (double)red[0]);
        atomicAdd(&g_neg_sum, 2.0 * (double)red[256]);
    }
}

__global__ void fl_finish_kernel(float* out, long long N) {
    double np = (double)g_num_pos;
    double total = (double)N * (double)N;
    double nn = total - np;
    double pt = (np > 0.0) ? 0.5 * g_pos_sum / np : 0.0;
    double nt = (nn > 0.0) ? 0.5 * g_neg_sum / nn : 0.0;
    out[0] = (float)(pt + nt);
}

extern "C" void kernel_launch(void* const* d_in, const int* in_sizes, int n_in,
                              void* d_out, int out_size) {
    const float* X = (const float*)d_in[0];
    const int* lab32 = (const int*)d_in[1];
    int N = in_sizes[1];
    int D = in_sizes[0] / N;

    if (D == 128 && N % 128 == 0 && (size_t)N * D <= 8192 * 128) {
        fl_prep_kernel<<<N / 8 + 1, 256>>>(X, lab32, N);
        int TR = N / 128, TC = N / 64;
        int nTiles = TR * TC - TR * (TR - 1);    // rows x 64-col upper triangle
        int grid = 444;                           // 3 CTAs x 148 SMs
        if (grid > nTiles) grid = nTiles;
        cudaFuncSetAttribute(fl_pairs_mma, cudaFuncAttributeMaxDynamicSharedMemorySize, SMEM_DYN);
        fl_pairs_mma<<<grid, 256, SMEM_DYN>>>(TR, TC, nTiles, grid, X, (float*)d_out, (long long)N);
    } else {
        fl_sq_kernel<<<N, 128>>>(X, N, D);
        fl_hist_kernel<<<1, 1024>>>(lab32, N);
        int T = (N + 63) / 64;
        int nb = T * (T + 1) / 2;
        fl_pairs_fp32<<<nb, 256>>>(X, N, D, T);
        fl_finish_kernel<<<1, 1>>>((float*)d_out, (long long)N);
    }
}

// round 11
// speedup vs baseline: 1.0878x; 1.0259x over previous
#include <cuda_runtime.h>
#include <cuda_bf16.h>

// FeaturesLoss: contrastive pairwise loss over N=8192 D=128 fp32 features.
//  pos_term: ANALYTIC per class: sum_c (2 n_c S2_c - 2 ||S1_c||^2).
//  neg_term: hinge fires only if dist_sq < 4; detect via bf16 mma.sync Gram tiles
//            vs constant threshold; flagged pairs recomputed EXACTLY from fp32 X.
// KEY CHANGE (R11): tile loads via 1-D bulk TMA (cp.async.bulk + mbarrier), ONE
// instruction per tile instead of 1024 x LDGSTS (rt=8cyc/op was the real floor).
// g_xb stored pre-swizzled in gmem (chunk c of row r at c^(r&7)) so contiguous
// bulk copies land conflict-free for ldmatrix.

#define MARGIN 2.0f
#define EPSV   1e-9f
#define SLACK_THR 6.0f
#define SLACK_EST 16.0f

__device__ double g_pos_sum;
__device__ double g_neg_sum;
__device__ unsigned long long g_num_pos;
__device__ unsigned g_done;
__device__ int g_thr_bits = 0x7f7fffff;
__device__ float g_sq[16384];
__device__ int   g_lab[16384];
__device__ int   g_cnt[64];
__device__ int   g_off[64];
__device__ int   g_list[16384];
__device__ __align__(256) unsigned char g_xb[8192 * 256];  // bf16, chunk-swizzled rows

__device__ __forceinline__ unsigned smem_u32(const void* p) {
    unsigned a;
    asm("{ .reg .u64 t; cvta.to.shared.u64 t, %1; cvt.u32.u64 %0, t; }" : "=r"(a) : "l"(p));
    return a;
}
__device__ __forceinline__ void ldsm_x4(unsigned& r0, unsigned& r1, unsigned& r2, unsigned& r3,
                                        unsigned addr) {
    asm volatile("ldmatrix.sync.aligned.m8n8.x4.shared.b16 {%0,%1,%2,%3}, [%4];"
                 : "=r"(r0), "=r"(r1), "=r"(r2), "=r"(r3) : "r"(addr));
}
__device__ __forceinline__ void mma_bf16(float* c, unsigned a0, unsigned a1, unsigned a2,
                                         unsigned a3, unsigned b0, unsigned b1) {
    asm volatile(
        "mma.sync.aligned.m16n8k16.row.col.f32.bf16.bf16.f32 "
        "{%0,%1,%2,%3},{%4,%5,%6,%7},{%8,%9},{%0,%1,%2,%3};"
        : "+f"(c[0]), "+f"(c[1]), "+f"(c[2]), "+f"(c[3])
        : "r"(a0), "r"(a1), "r"(a2), "r"(a3), "r"(b0), "r"(b1));
}
#define TMA_BULK(dst, src, bytes, mbar) \
    asm volatile("cp.async.bulk.shared::cluster.global.mbarrier::complete_tx::bytes [%0], [%1], %2, [%3];" \
        :: "r"(dst), "l"(src), "r"(bytes), "r"(mbar) : "memory")
#define MB_INIT(mb, c) asm volatile("mbarrier.init.shared.b64 [%0], %1;" :: "r"(mb), "r"(c) : "memory")
#define MB_EXPECT_TX(mb, tx) \
    asm volatile("mbarrier.arrive.expect_tx.shared.b64 _, [%0], %1;" :: "r"(mb), "r"(tx) : "memory")
#define FENCE_ASYNC() asm volatile("fence.proxy.async.shared::cta;" ::: "memory")

__device__ __forceinline__ void mb_wait(unsigned mb, unsigned parity) {
    asm volatile(
        "{\n\t.reg .pred P1;\n\t"
        "WAIT_LOOP_%=:\n\t"
        "mbarrier.try_wait.parity.acquire.cta.shared::cta.b64 P1, [%0], %1, 0x989680;\n\t"
        "@P1 bra.uni WAIT_DONE_%=;\n\t"
        "bra.uni WAIT_LOOP_%=;\n\t"
        "WAIT_DONE_%=:\n\t}"
        :: "r"(mb), "r"(parity) : "memory");
}

// ---------------- prep + hist/lists (one launch) ----------------
__global__ void fl_prep_kernel(const float* __restrict__ X,
                               const int* __restrict__ lab32, int N) {
    if ((int)blockIdx.x == N / 8) {
        __shared__ int cnt[64], soff[64], scur[64];
        __shared__ int hi_nonzero;
        if (threadIdx.x == 0) {
            hi_nonzero = 0; g_pos_sum = 0.0; g_neg_sum = 0.0; g_done = 0;
        }
        if (threadIdx.x < 64) { cnt[threadIdx.x] = 0; scur[threadIdx.x] = 0; }
        __syncthreads();
        int local = 0;
        for (int i = threadIdx.x; i < N / 2; i += blockDim.x)
            if (lab32[2 * i + 1] != 0) local++;
        if (local) atomicAdd(&hi_nonzero, local);
        __syncthreads();
        const bool is_int64 = (hi_nonzero < N / 8);
        for (int i = threadIdx.x; i < N; i += blockDim.x) {
            int l = (is_int64 ? lab32[2 * i] : lab32[i]) & 63;
            g_lab[i] = l;
            atomicAdd(&cnt[l], 1);
        }
        __syncthreads();
        if (threadIdx.x == 0) {
            unsigned long long np = 0;
            int run = 0;
            for (int c = 0; c < 64; c++) {
                np += (unsigned long long)cnt[c] * (unsigned long long)cnt[c];
                soff[c] = run;
                run += cnt[c];
                g_cnt[c] = cnt[c];
            }
            g_num_pos = np;
        }
        __syncthreads();
        if (threadIdx.x < 64) g_off[threadIdx.x] = soff[threadIdx.x];
        for (int i = threadIdx.x; i < N; i += blockDim.x) {
            int l = g_lab[i];
            int p = atomicAdd(&scur[l], 1);
            g_list[soff[l] + p] = i;
        }
        return;
    }
    __shared__ float wmin[8];
    const int w = threadIdx.x >> 5;
    const int row = blockIdx.x * 8 + w;
    const int lane = threadIdx.x & 31;
    float4 v = *(const float4*)&X[(size_t)row * 128 + lane * 4];
    float s = v.x * v.x;
    s = fmaf(v.y, v.y, s);
    s = fmaf(v.z, v.z, s);
    s = fmaf(v.w, v.w, s);
    for (int o = 16; o; o >>= 1) s += __shfl_down_sync(0xffffffffu, s, o);
    if (lane == 0) { g_sq[row] = s; wmin[w] = s; }
    __nv_bfloat162 p0 = __floats2bfloat162_rn(v.x, v.y);
    __nv_bfloat162 p1 = __floats2bfloat162_rn(v.z, v.w);
    uint2 packed;
    packed.x = *(unsigned*)&p0;
    packed.y = *(unsigned*)&p1;
    // Swizzled store: lane covers logical 16B-chunk lane>>1, half (lane&1).
    unsigned chunk = lane >> 1;
    unsigned phys = ((chunk ^ (row & 7)) << 4) + ((lane & 1) << 3);
    *(uint2*)(g_xb + (size_t)row * 256 + phys) = packed;
    __syncthreads();
    if (threadIdx.x == 0) {
        float m = wmin[0];
        #pragma unroll
        for (int i = 1; i < 8; i++) m = fminf(m, wmin[i]);
        atomicMin(&g_thr_bits, __float_as_int(m));
    }
}

// 128-row x 64-col tiles over the upper triangle: row r owns cols [2r, TC).
__device__ __forceinline__ int tri_base2(int r, int TC) {
    return TC * r - r * (r - 1);
}

// ---------------- persistent bf16 mma.sync pairs kernel (D=128) ----------------
#define A_OFF   0
#define B0_OFF  32768
#define B1_OFF  49152
#define MISC    65536
#define MB_A    (MISC + 0)
#define MB_B0   (MISC + 8)
#define MB_B1   (MISC + 16)
#define SMEM_DYN (MISC + 1280)

// Per-class analytic pos sum.
__device__ void class_phase(int c, const float* __restrict__ X, float* scratch) {
    int n = g_cnt[c];
    if (n == 0) return;
    int off = g_off[c];
    int tid = threadIdx.x;
    if (tid < 128) {
        float s1 = 0.f;
        #pragma unroll 4
        for (int m = 0; m < n; m++)
            s1 += X[(size_t)g_list[off + m] * 128 + tid];
        scratch[tid] = s1 * s1;
    } else {
        float s2 = 0.f;
        for (int m = tid - 128; m < n; m += 128)
            s2 += g_sq[g_list[off + m]];
        for (int o = 16; o; o >>= 1) s2 += __shfl_down_sync(0xffffffffu, s2, o);
        if (((tid - 128) & 31) == 0) scratch[128 + ((tid - 128) >> 5)] = s2;
    }
    __syncthreads();
    if (tid == 0) {
        float s1sq = 0.f;
        for (int d = 0; d < 128; d++) s1sq += scratch[d];
        float S2 = scratch[128] + scratch[129] + scratch[130] + scratch[131];
        double pos_c = 2.0 * (double)n * (double)S2 - 2.0 * (double)s1sq;
        atomicAdd(&g_pos_sum, pos_c);
    }
    __syncthreads();
}

__global__ void __launch_bounds__(256, 3) fl_pairs_mma(int TR, int TC, int nTiles, int nCTA,
                                                       const float* __restrict__ X,
                                                       float* out, long long N) {
    extern __shared__ char sm[];
    const unsigned sb = smem_u32(sm);
    float* scratch = (float*)(sm + MISC + 64);   // 132 floats (class phase)
    float* red = (float*)(sm + MISC + 640);      // 8 floats

    const int tid = threadIdx.x;
    const int wid = tid >> 5;
    const int lane = tid & 31;

    // mbarriers
    if (tid == 0) {
        MB_INIT(sb + (MB_A - MISC) + MISC, 1);   // = sb + MB_A offset
        MB_INIT(sb + MB_B0, 1);
        MB_INIT(sb + MB_B1, 1);
    }
    FENCE_ASYNC();
    __syncthreads();
    const unsigned mbA = sb + MB_A;
    const unsigned mbB[2] = { sb + MB_B0, sb + MB_B1 };
    const unsigned bufB[2] = { sb + B0_OFF, sb + B1_OFF };
    const unsigned aBase = sb + A_OFF;

    // Weighted contiguous chunks: class CTAs (cta<64) get 1 fewer tile.
    const int cta = blockIdx.x;
    const int W = ((nTiles / nCTA) > 2 && nCTA >= 64) ? 1 : 0;
    const int vTotal = nTiles + 64 * W;
    const int vbase = vTotal / nCTA, vrem = vTotal % nCTA;
    const int vstart = cta * vbase + min(cta, vrem);
    const int vcount = vbase + (cta < vrem ? 1 : 0);
    const int start = vstart - W * min(cta, 64);
    const int count = vcount - (cta < 64 ? W : 0);

    // Uniform load bookkeeping (all threads track; tid0 issues).
    int cntA = 0, seenA = 0;
    int cntB0 = 0, cntB1 = 0, seenB0 = 0, seenB1 = 0;
    int bIssue = 0, bCons = 0;

    // Decode starting tile; issue its loads before the class phase.
    int r = 0, c = 0;
    if (count > 0) {
        while (r < TR - 1 && tri_base2(r + 1, TC) <= start) r++;
        c = 2 * r + (start - tri_base2(r, TC));
        if (tid == 0) {
            MB_EXPECT_TX(mbA, 32768u);
            TMA_BULK(aBase, g_xb + (size_t)r * 32768, 32768u, mbA);
        }
        cntA = 1;
        if ((c >> 1) != r) {
            if (tid == 0) {
                MB_EXPECT_TX(mbB[0], 16384u);
                TMA_BULK(bufB[0], g_xb + (size_t)c * 16384, 16384u, mbB[0]);
            }
            cntB0 = 1;
            bIssue = 1;
        }
    }

    const float gmin = __int_as_float(g_thr_bits);
    const float thrmin = gmin - 2.0f - SLACK_THR;

    for (int cc = blockIdx.x; cc < 64; cc += nCTA)
        class_phase(cc, X, scratch);

    // Warp tiling: 4(M) x 2(N) warps; warp tile 32x32.
    const int Moff = (wid >> 1) * 32;
    const int Noff = (wid & 1) * 32;
    const int arow = (lane & 7) + ((lane >> 3) & 1) * 8;
    const int achi = (lane >> 4);          // A chunk offset (0/1)
    const int brow = (lane & 7) + ((lane >> 4) & 1) * 8;
    const int bchi = ((lane >> 3) & 1);    // B chunk offset (0/1)
    const int sxor = lane & 7;             // swizzle XOR (= arow&7 = brow&7)
    const int grp = lane >> 2, q = lane & 3;

    float ns = 0.f;

    if (count > 0) {
        for (int s = 0; s < count; s++) {
            const bool diag = ((c >> 1) == r);
            const int rowA = r * 128, colB = c * 64;
            int nc = c + 1, nr = r;
            if (nc == TC) { nr = r + 1; nc = 2 * nr; }
            const bool more = (s + 1 < count);
            const bool aChange = more && (nr != r);
            const bool nextDiag = ((nc >> 1) == nr);

            __syncthreads();   // everyone done with previous tile's buffers

            // Prefetch next tile's B (next tile non-diag; hidden under this MMA).
            if (more && !nextDiag) {
                if (tid == 0) {
                    MB_EXPECT_TX(mbB[bIssue], 16384u);
                    TMA_BULK(bufB[bIssue], g_xb + (size_t)nc * 16384, 16384u, mbB[bIssue]);
                }
                if (bIssue == 0) cntB0++; else cntB1++;
                bIssue ^= 1;
            }

            // Waits for this tile's data.
            if (cntA > seenA) { mb_wait(mbA, (unsigned)((cntA - 1) & 1)); seenA = cntA; }
            unsigned bBase;
            if (diag) {
                bBase = aBase + (unsigned)((c - 2 * r) * 16384);
            } else {
                if (bCons == 0) {
                    if (cntB0 > seenB0) { mb_wait(mbB[0], (unsigned)((cntB0 - 1) & 1)); seenB0 = cntB0; }
                } else {
                    if (cntB1 > seenB1) { mb_wait(mbB[1], (unsigned)((cntB1 - 1) & 1)); seenB1 = cntB1; }
                }
                bBase = bufB[bCons];
                bCons ^= 1;
            }

            float acc[2][4][4];
            #pragma unroll
            for (int mi = 0; mi < 2; mi++)
                #pragma unroll
                for (int ni = 0; ni < 4; ni++)
                    #pragma unroll
                    for (int v = 0; v < 4; v++) acc[mi][ni][v] = 0.f;

            #pragma unroll
            for (int ks = 0; ks < 8; ks++) {
                unsigned physB = (unsigned)(((2 * ks + bchi) ^ sxor) << 4);
                unsigned physA = (unsigned)(((2 * ks + achi) ^ sxor) << 4);
                unsigned b[2][4];
                #pragma unroll
                for (int p = 0; p < 2; p++) {
                    unsigned bd = bBase + (unsigned)((Noff + p * 16 + brow) * 256) + physB;
                    ldsm_x4(b[p][0], b[p][1], b[p][2], b[p][3], bd);
                }
                #pragma unroll
                for (int mi = 0; mi < 2; mi++) {
                    unsigned a0, a1, a2, a3;
                    unsigned ad = aBase + (unsigned)((Moff + mi * 16 + arow) * 256) + physA;
                    ldsm_x4(a0, a1, a2, a3, ad);
                    #pragma unroll
                    for (int ni = 0; ni < 4; ni++)
                        mma_bf16(acc[mi][ni], a0, a1, a2, a3,
                                 b[ni >> 1][(ni & 1) * 2], b[ni >> 1][(ni & 1) * 2 + 1]);
                }
            }

            // A-row change: wait for all warps' A reads before overwriting.
            if (aChange) {
                __syncthreads();
                if (tid == 0) {
                    MB_EXPECT_TX(mbA, 32768u);
                    TMA_BULK(aBase, g_xb + (size_t)nr * 32768, 32768u, mbA);
                }
                cntA++;
            }

            // Fast epilogue: hinge possible only if some acc exceeds threshold.
            float mx = acc[0][0][0];
            #pragma unroll
            for (int mi = 0; mi < 2; mi++)
                #pragma unroll
                for (int ni = 0; ni < 4; ni++)
                    #pragma unroll
                    for (int v = 0; v < 4; v++)
                        mx = fmaxf(mx, acc[mi][ni][v]);
            #pragma unroll
            for (int o = 16; o; o >>= 1)
                mx = fmaxf(mx, __shfl_xor_sync(0xffffffffu, mx, o));

            if (mx > thrmin) {
                // Rare path: per-element estimate; flagged pairs recomputed exactly.
                #pragma unroll
                for (int mi = 0; mi < 2; mi++) {
                    #pragma unroll
                    for (int ni = 0; ni < 4; ni++) {
                        #pragma unroll
                        for (int rr = 0; rr < 2; rr++) {
                            #pragma unroll
                            for (int cc2 = 0; cc2 < 2; cc2++) {
                                int rl = Moff + mi * 16 + grp + rr * 8;
                                int cl = Noff + ni * 8 + q * 2 + cc2;
                                float av = acc[mi][ni][rr * 2 + cc2];
                                int ig = rowA + rl, jg = colB + cl;
                                float est = g_sq[ig] + g_sq[jg] - 2.f * av;
                                if (est < SLACK_EST) {
                                    if (g_lab[ig] != g_lab[jg] && (!diag || jg > ig)) {
                                        const float* xi = &X[(size_t)ig * 128];
                                        const float* xj = &X[(size_t)jg * 128];
                                        float d = 0.f;
                                        for (int k = 0; k < 128; k++) {
                                            float df = xi[k] - xj[k];
                                            d = fmaf(df, df, d);
                                        }
                                        if (d < 4.f) {
                                            float t = MARGIN - sqrtf(d + EPSV);
                                            if (t > 0.f) ns = fmaf(t, t, ns);
                                        }
                                    }
                                }
                            }
                        }
                    }
                }
            }

            r = nr; c = nc;
        }
    }

    // Final reduction + completion.
    for (int o = 16; o; o >>= 1) ns += __shfl_down_sync(0xffffffffu, ns, o);
    __syncthreads();
    if (lane == 0) red[wid] = ns;
    __syncthreads();
    __shared__ unsigned s_last;
    if (tid == 0) {
        float tns = 0.f;
        #pragma unroll
        for (int w = 0; w < 8; w++) tns += red[w];
        if (tns != 0.f) atomicAdd(&g_neg_sum, 2.0 * (double)tns);
        __threadfence();
        s_last = atomicAdd(&g_done, 1u);
    }
    __syncthreads();
    if (tid == 0 && s_last == (unsigned)(nCTA - 1)) {
        double np = (double)g_num_pos;
        double total = (double)N * (double)N;
        double nn = total - np;
        double pt = (np > 0.0) ? 0.5 * g_pos_sum / np : 0.0;
        double nt = (nn > 0.0) ? 0.5 * g_neg_sum / nn : 0.0;
        out[0] = (float)(pt + nt);
        g_done = 0;                 // reset for next graph replay
        g_thr_bits = 0x7f7fffff;    // reset threshold accumulator
    }
}

// ---------------- fp32 fallback (any D / N) ----------------
__global__ void fl_sq_kernel(const float* __restrict__ X, int N, int D) {
    int row = blockIdx.x;
    float s = 0.f;
    for (int k = threadIdx.x; k < D; k += blockDim.x) {
        float v = X[(size_t)row * D + k];
        s = fmaf(v, v, s);
    }
    for (int o = 16; o; o >>= 1) s += __shfl_down_sync(0xffffffffu, s, o);
    __shared__ float ws[32];
    int lane = threadIdx.x & 31, w = threadIdx.x >> 5;
    if (lane == 0) ws[w] = s;
    __syncthreads();
    if (w == 0) {
        int nw = (blockDim.x + 31) >> 5;
        s = (lane < nw) ? ws[lane] : 0.f;
        for (int o = 16; o; o >>= 1) s += __shfl_down_sync(0xffffffffu, s, o);
        if (lane == 0) g_sq[row] = s;
    }
}

__global__ void fl_hist_kernel(const int* __restrict__ lab32, int N) {
    __shared__ int cnt[64];
    __shared__ int hi_nonzero;
    if (threadIdx.x == 0) { hi_nonzero = 0; g_pos_sum = 0.0; g_neg_sum = 0.0; }
    if (threadIdx.x < 64) cnt[threadIdx.x] = 0;
    __syncthreads();
    int local = 0;
    for (int i = threadIdx.x; i < N / 2; i += blockDim.x)
        if (lab32[2 * i + 1] != 0) local++;
    if (local) atomicAdd(&hi_nonzero, local);
    __syncthreads();
    const bool is_int64 = (hi_nonzero < N / 8);
    for (int i = threadIdx.x; i < N; i += blockDim.x) {
        int l = (is_int64 ? lab32[2 * i] : lab32[i]) & 63;
        g_lab[i] = l;
        atomicAdd(&cnt[l], 1);
    }
    __syncthreads();
    if (threadIdx.x == 0) {
        unsigned long long np = 0;
        for (int c = 0; c < 64; c++)
            np += (unsigned long long)cnt[c] * (unsigned long long)cnt[c];
        g_num_pos = np;
    }
}

__device__ __forceinline__ int tri_base(int bi, int T) {
    return bi * T - (bi * (bi - 1)) / 2;
}
__device__ __forceinline__ void tri_decode(int L, int T, int& bi, int& bj) {
    bi = 0;
    while (bi < T - 1 && tri_base(bi + 1, T) <= L) bi++;
    bj = bi + (L - tri_base(bi, T));
}

__global__ __launch_bounds__(256)
void fl_pairs_fp32(const float* __restrict__ X, int N, int D, int T) {
    int bi, bj;
    tri_decode(blockIdx.x, T, bi, bj);
    const int rowA = bi * 64, rowB = bj * 64;
    const bool diag = (bi == bj);
    __shared__ float As[64][65];
    __shared__ float Bs[64][65];
    const int tid = threadIdx.x, tx = tid & 15, ty = tid >> 4;
    float acc[4][4] = {};
    for (int kc = 0; kc < D; kc += 64) {
        __syncthreads();
        #pragma unroll
        for (int i = 0; i < 4; i++) {
            int lin = tid + 256 * i;
            int r = lin >> 4, kq = (lin & 15) << 2;
            if (kc + kq < D) {
                float4 va = *(const float4*)&X[(size_t)(rowA + r) * D + kc + kq];
                As[r][kq] = va.x; As[r][kq + 1] = va.y; As[r][kq + 2] = va.z; As[r][kq + 3] = va.w;
                float4 vb = *(const float4*)&X[(size_t)(rowB + r) * D + kc + kq];
                Bs[r][kq] = vb.x; Bs[r][kq + 1] = vb.y; Bs[r][kq + 2] = vb.z; Bs[r][kq + 3] = vb.w;
            }
        }
        __syncthreads();
        int klim = min(64, D - kc);
        for (int k = 0; k < klim; k++) {
            float a0 = As[ty * 4][k], a1 = As[ty * 4 + 1][k], a2 = As[ty * 4 + 2][k], a3 = As[ty * 4 + 3][k];
            float b0 = Bs[tx * 4][k], b1 = Bs[tx * 4 + 1][k], b2 = Bs[tx * 4 + 2][k], b3 = Bs[tx * 4 + 3][k];
            acc[0][0] = fmaf(a0, b0, acc[0][0]); acc[0][1] = fmaf(a0, b1, acc[0][1]);
            acc[0][2] = fmaf(a0, b2, acc[0][2]); acc[0][3] = fmaf(a0, b3, acc[0][3]);
            acc[1][0] = fmaf(a1, b0, acc[1][0]); acc[1][1] = fmaf(a1, b1, acc[1][1]);
            acc[1][2] = fmaf(a1, b2, acc[1][2]); acc[1][3] = fmaf(a1, b3, acc[1][3]);
            acc[2][0] = fmaf(a2, b0, acc[2][0]); acc[2][1] = fmaf(a2, b1, acc[2][1]);
            acc[2][2] = fmaf(a2, b2, acc[2][2]); acc[2][3] = fmaf(a2, b3, acc[2][3]);
            acc[3][0] = fmaf(a3, b0, acc[3][0]); acc[3][1] = fmaf(a3, b1, acc[3][1]);
            acc[3][2] = fmaf(a3, b2, acc[3][2]); acc[3][3] = fmaf(a3, b3, acc[3][3]);
        }
    }
    const int i0 = rowA + ty * 4, j0 = rowB + tx * 4;
    float sqi[4], sqj[4]; int li[4], lj[4];
    #pragma unroll
    for (int m = 0; m < 4; m++) { sqi[m] = g_sq[i0 + m]; li[m] = g_lab[i0 + m]; }
    #pragma unroll
    for (int n = 0; n < 4; n++) { sqj[n] = g_sq[j0 + n]; lj[n] = g_lab[j0 + n]; }
    float ps = 0.f, nsl = 0.f;
    #pragma unroll
    for (int m = 0; m < 4; m++)
        #pragma unroll
        for (int n = 0; n < 4; n++) {
            if (diag && (j0 + n) <= (i0 + m)) continue;
            float d = fmaxf(sqi[m] + sqj[n] - 2.f * acc[m][n], 0.f);
            if (li[m] == lj[n]) ps += d;
            else { float t = MARGIN - sqrtf(d + EPSV); if (t > 0.f) nsl = fmaf(t, t, nsl); }
        }
    __syncthreads();
    float* red = &As[0][0];
    red[tid] = ps; red[256 + tid] = nsl;
    __syncthreads();
    for (int s = 128; s; s >>= 1) {
        if (tid < s) { red[tid] += red[tid + s]; red[256 + tid] += red[256 + tid + s]; }
        __syncthreads();
    }
    if (tid == 0) {
        atomicAdd(&g_pos_sum, 2.0 * (double)red[0]);
        atomicAdd(&g_neg_sum, 2.0 * (double)red[256]);
    }
}

__global__ void fl_finish_kernel(float* out, long long N) {
    double np = (double)g_num_pos;
    double total = (double)N * (double)N;
    double nn = total - np;
    double pt = (np > 0.0) ? 0.5 * g_pos_sum / np : 0.0;
    double nt = (nn > 0.0) ? 0.5 * g_neg_sum / nn : 0.0;
    out[0] = (float)(pt + nt);
}

extern "C" void kernel_launch(void* const* d_in, const int* in_sizes, int n_in,
                              void* d_out, int out_size) {
    const float* X = (const float*)d_in[0];
    const int* lab32 = (const int*)d_in[1];
    int N = in_sizes[1];
    int D = in_sizes[0] / N;

    if (D == 128 && N % 128 == 0 && (size_t)N * D <= 8192 * 128) {
        fl_prep_kernel<<<N / 8 + 1, 256>>>(X, lab32, N);
        int TR = N / 128, TC = N / 64;
        int nTiles = TR * TC - TR * (TR - 1);    // 128-row x 64-col upper triangle
        int grid = 444;                           // 3 CTAs x 148 SMs
        if (grid > nTiles) grid = nTiles;
        cudaFuncSetAttribute(fl_pairs_mma, cudaFuncAttributeMaxDynamicSharedMemorySize, SMEM_DYN);
        fl_pairs_mma<<<grid, 256, SMEM_DYN>>>(TR, TC, nTiles, grid, X, (float*)d_out, (long long)N);
    } else {
        fl_sq_kernel<<<N, 128>>>(X, N, D);
        fl_hist_kernel<<<1, 1024>>>(lab32, N);
        int T = (N + 63) / 64;
        int nb = T * (T + 1) / 2;
        fl_pairs_fp32<<<nb, 256>>>(X, N, D, T);
        fl_finish_kernel<<<1, 1>>>((float*)d_out, (long long)N);
    }
}